// round 13
// baseline (speedup 1.0000x reference)
#include <cuda_runtime.h>
#include <cuda_bf16.h>
#include <cstdint>
#include <math.h>

#define DEV_INLINE __device__ __forceinline__

static constexpr int B_ = 16, C_ = 256, H_ = 128, W_ = 128;
static constexpr int CS = 512;
static constexpr int TOK_HF = 1024;
static constexpr int M_HF = 3 * B_ * TOK_HF;     // 49152
static constexpr int M_LF = B_ * 256;            // 4096

// ---------------- scratch ----------------
__device__ __nv_bfloat16 g_z[3ULL * B_ * C_ * TOK_HF];   // [band][b][c][tok] bf16
__device__ float g_ps[(size_t)B_ * CS * 256];            // [b][s][tok]
__device__ float g_Hlf[(size_t)M_LF * 512];              // RAW hidden (lf) fp32
__device__ float g_ktok[(size_t)M_LF * C_];
__device__ float g_gate[(size_t)M_LF * C_];
__device__ float g_alpha[3 * B_ * TOK_HF];
__device__ float g_wt[5ULL * 512 * 256];                 // transposed weights [n][k] fp32
__device__ __nv_bfloat16 g_wth[2ULL * 512 * 256];        // bf16: [0]=hf_w1t(512n,256k), [1]=hf_w2t'(256n,512k)
__device__ float2 g_stats_lf[(size_t)M_LF * 2];
__device__ float g_c1[2 * 256];
__device__ float g_bp[2 * 256];

// ---------------- weight transpose (+ LN-weight folding + bf16 copies) ----------------
__global__ void transpose5_kernel(const float* __restrict__ w0, const float* __restrict__ w1,
                                  const float* __restrict__ w2, const float* __restrict__ w3,
                                  const float* __restrict__ w4,
                                  const float* __restrict__ hf_lnw, const float* __restrict__ lf_lnw)
{
    __shared__ float tile[32][33];
    int mi = blockIdx.z;
    const float* in; int R, Cc; const float* lnw = nullptr;
    switch (mi) {
        case 0: in = w0; R = 256; Cc = 512; break;                 // hf_w1 -> [512n][256k]
        case 1: in = w1; R = 512; Cc = 256; lnw = hf_lnw; break;   // hf_w2' -> [256n][512k]
        case 2: in = w2; R = 512; Cc = 256; break;
        case 3: in = w3; R = 256; Cc = 512; break;
        default: in = w4; R = 512; Cc = 256; lnw = lf_lnw; break;
    }
    float* out = g_wt + (size_t)mi * 512 * 256;
    int bx = blockIdx.x * 32, by = blockIdx.y * 32;
    if (bx >= Cc || by >= R) return;
    int tx = threadIdx.x, ty = threadIdx.y;
#pragma unroll
    for (int j = 0; j < 32; j += 8) {
        int row = by + ty + j;
        float v = in[(size_t)row * Cc + bx + tx];
        if (lnw) v *= __ldg(lnw + row);
        tile[ty + j][tx] = v;
    }
    __syncthreads();
#pragma unroll
    for (int j = 0; j < 32; j += 8) {
        float v = tile[tx][ty + j];
        size_t oidx = (size_t)(bx + ty + j) * R + by + tx;
        out[oidx] = v;
        if (mi == 0) g_wth[oidx] = __float2bfloat16(v);
        if (mi == 1) g_wth[512 * 256 + oidx] = __float2bfloat16(v);
    }
}

// fold: c1[n]=col-sums of W2'; bp[n]=b2[n]+lnb@W2
__global__ void fold_kernel(const float* __restrict__ w2a, const float* __restrict__ lnba,
                            const float* __restrict__ b2a,
                            const float* __restrict__ w2b, const float* __restrict__ lnbb,
                            const float* __restrict__ b2b)
{
    int mi = blockIdx.x;
    int n = threadIdx.x;
    const float* wt = g_wt + (size_t)(mi ? 4 : 1) * 512 * 256;
    const float* w2 = mi ? w2b : w2a;
    const float* lnb = mi ? lnbb : lnba;
    const float* b2 = mi ? b2b : b2a;
    float s1 = 0.f, s2 = 0.f;
    for (int k = 0; k < 512; k++) {
        s1 += wt[(size_t)n * 512 + k];
        s2 += lnb[k] * w2[(size_t)k * 256 + n];
    }
    g_c1[mi * 256 + n] = s1;
    g_bp[mi * 256 + n] = b2[n] + s2;
}

// ---------------- K1: Haar bands -> abs-pooled z tokens (bf16 out) ----------------
__global__ void haar_z_kernel(const float* __restrict__ xb)
{
    int tid = threadIdx.x;
    int tk = blockIdx.x * 256 + tid;
    int c = blockIdx.y, b = blockIdx.z;
    int ti = tk >> 5, tj = tk & 31;
    const float* base = xb + ((size_t)(b * C_ + c) * H_ + 4 * ti) * W_ + 4 * tj;
    float4 r0 = *(const float4*)(base);
    float4 r1 = *(const float4*)(base + W_);
    float4 r2 = *(const float4*)(base + 2 * W_);
    float4 r3 = *(const float4*)(base + 3 * W_);
    float zh = 0.f, zv = 0.f, zd = 0.f;
#define HBLK(p00, p01, p10, p11) \
    zh += fabsf((p00) - (p01) + (p10) - (p11)); \
    zv += fabsf((p00) + (p01) - (p10) - (p11)); \
    zd += fabsf((p00) - (p01) - (p10) + (p11));
    HBLK(r0.x, r0.y, r1.x, r1.y)
    HBLK(r0.z, r0.w, r1.z, r1.w)
    HBLK(r2.x, r2.y, r3.x, r3.y)
    HBLK(r2.z, r2.w, r3.z, r3.w)
#undef HBLK
    const float s = 0.0625f;
    size_t base_o = ((size_t)(b) * C_ + c) * TOK_HF + tk;
    const size_t BS = (size_t)B_ * C_ * TOK_HF;
    g_z[base_o]          = __float2bfloat16(zh * s);
    g_z[BS + base_o]     = __float2bfloat16(zv * s);
    g_z[2 * BS + base_o] = __float2bfloat16(zd * s);
}

// ---------------- K2: 4x4 mean-pool of x_small ----------------
__global__ void pool_small_kernel(const float* __restrict__ xsm)
{
    int s = blockIdx.x, b = blockIdx.y;
    const float* src = xsm + ((size_t)(b * CS + s)) * 64 * 64;
    int t = threadIdx.x;
    int tj = t & 15, ti = t >> 4;
    float sum = 0.f;
#pragma unroll
    for (int r = 0; r < 4; r++) {
        float4 v = *(const float4*)(src + (4 * ti + r) * 64 + 4 * tj);
        sum += v.x + v.y + v.z + v.w;
    }
    g_ps[((size_t)(b * CS + s)) * 256 + t] = sum * (1.f / 16.f);
}

// ---------------- asm helpers ----------------
DEV_INLINE void mma8(float* c, const unsigned* a, const unsigned* b) {
    asm volatile("mma.sync.aligned.m16n8k8.row.col.f32.tf32.tf32.f32 "
                 "{%0,%1,%2,%3}, {%4,%5,%6,%7}, {%8,%9}, {%0,%1,%2,%3};"
                 : "+f"(c[0]), "+f"(c[1]), "+f"(c[2]), "+f"(c[3])
                 : "r"(a[0]), "r"(a[1]), "r"(a[2]), "r"(a[3]),
                   "r"(b[0]), "r"(b[1]));
}
DEV_INLINE void mma16(float* c, const unsigned* a, const unsigned* b) {
    asm volatile("mma.sync.aligned.m16n8k16.row.col.f32.bf16.bf16.f32 "
                 "{%0,%1,%2,%3}, {%4,%5,%6,%7}, {%8,%9}, {%0,%1,%2,%3};"
                 : "+f"(c[0]), "+f"(c[1]), "+f"(c[2]), "+f"(c[3])
                 : "r"(a[0]), "r"(a[1]), "r"(a[2]), "r"(a[3]),
                   "r"(b[0]), "r"(b[1]));
}
DEV_INLINE void ldsm4(unsigned& r0, unsigned& r1, unsigned& r2, unsigned& r3, uint32_t addr) {
    asm volatile("ldmatrix.sync.aligned.m8n8.x4.shared.b16 {%0,%1,%2,%3}, [%4];"
                 : "=r"(r0), "=r"(r1), "=r"(r2), "=r"(r3) : "r"(addr));
}
DEV_INLINE void cp16(uint32_t s, const void* g) {
    asm volatile("cp.async.cg.shared.global [%0], [%1], 16;" :: "r"(s), "l"(g));
}
DEV_INLINE void cp8(uint32_t s, const void* g) {
    asm volatile("cp.async.ca.shared.global [%0], [%1], 8;" :: "r"(s), "l"(g));
}
DEV_INLINE void cp_commit() { asm volatile("cp.async.commit_group;"); }
template<int NN> DEV_INLINE void cp_wait() { asm volatile("cp.async.wait_group %0;" :: "n"(NN)); }

// ---------------- tf32 64x256-tile GEMM (R6-proven, lf chain) ----------------
template<int K, int AMODE, int EPI, int OSTRIDE>
__global__ void __launch_bounds__(256, 2)
gemm256_kernel(const float* __restrict__ A, const float* __restrict__ Bt,
               const float* __restrict__ bias, const float* __restrict__ p0,
               float* __restrict__ out, float2* __restrict__ stats,
               const float* __restrict__ c1)
{
    constexpr int KC = 32, SW = 36, SWB = SW * 4, NIT = K / KC, NN = 256;
    constexpr int MT = 2;

    extern __shared__ __align__(16) float dsm[];
    float* As = dsm;
    float* Bs = As + 2 * 64 * SW;
    float* sred = Bs + 2 * NN * SW;
    float* ssred = sred + 256;

    int tid = threadIdx.x;
    int lane = tid & 31, warp = tid >> 5;
    int wn = warp & 3, wm = warp >> 2;
    int gid = lane >> 2, q4 = lane & 3;
    int m0 = blockIdx.x * 64;
    int n0 = blockIdx.y * 256;

    const float* Ab; int astride = 0;
    if (AMODE == 1) { Ab = A + (size_t)(m0 >> 8) * (CS * 256) + (m0 & 255); astride = 256; }
    else { Ab = A + (size_t)m0 * K; }
    const float* BtB = Bt + (size_t)n0 * K;

    uint32_t smem_a = (uint32_t)__cvta_generic_to_shared(As);
    uint32_t smem_b = (uint32_t)__cvta_generic_to_shared(Bs);

    int la_m = tid & 63, la_kg = tid >> 6;
    float areg[8];
    auto load_A = [&](int k0) {
        if (AMODE == 1) {
#pragma unroll
            for (int i = 0; i < 8; i++)
                areg[i] = __ldg(Ab + (size_t)(k0 + la_kg * 8 + i) * astride + la_m);
        }
    };
    auto sts_A = [&](int st) {
        if (AMODE == 1) {
            float* p = As + st * 64 * SW + la_m * SW + la_kg * 8;
            *(float4*)(p)     = make_float4(areg[0], areg[1], areg[2], areg[3]);
            *(float4*)(p + 4) = make_float4(areg[4], areg[5], areg[6], areg[7]);
        }
    };
    auto cp_stage = [&](int st, int k0) {
        if (AMODE == 2) {
#pragma unroll
            for (int j = 0; j < 2; j++) {
                int idx = tid + j * 256;
                int m = idx >> 3, kq = idx & 7;
                cp16(smem_a + (uint32_t)((st * 64 + m) * SW + kq * 4) * 4,
                     Ab + (size_t)m * K + k0 + kq * 4);
            }
        }
#pragma unroll
        for (int j = 0; j < 8; j++) {
            int idx = tid + j * 256;
            int n = idx >> 3, kc = idx & 7;
            cp16(smem_b + (uint32_t)((st * NN + n) * SW + kc * 4) * 4,
                 BtB + (size_t)n * K + k0 + kc * 4);
        }
        cp_commit();
    };

    int ra = lane & 15;
    int ca = (lane & 16) ? 16 : 0;
    int rb = (lane & 7) + ((lane >> 4) << 3);
    int cb = (lane & 8) ? 16 : 0;

    float acc[MT][8][4];
#pragma unroll
    for (int mi = 0; mi < MT; mi++)
#pragma unroll
        for (int ni = 0; ni < 8; ni++)
#pragma unroll
            for (int e = 0; e < 4; e++) acc[mi][ni][e] = 0.f;

    load_A(0);
    cp_stage(0, 0);
    sts_A(0);
    if (NIT > 1) load_A(KC);

    for (int it = 0; it < NIT; it++) {
        int cur = it & 1;
        bool more = (it + 1 < NIT);
        cp_wait<0>();
        __syncthreads();
        if (more) {
            cp_stage(cur ^ 1, (it + 1) * KC);
            sts_A(cur ^ 1);
        }
        if (it + 2 < NIT) load_A((it + 2) * KC);

        uint32_t abase = smem_a + (uint32_t)(cur * 64 * SW) * 4;
        uint32_t bbase = smem_b + (uint32_t)(cur * NN * SW) * 4;
#pragma unroll
        for (int kk = 0; kk < KC; kk += 8) {
            unsigned afr[MT][4];
#pragma unroll
            for (int mi = 0; mi < MT; mi++)
                ldsm4(afr[mi][0], afr[mi][1], afr[mi][2], afr[mi][3],
                      abase + (uint32_t)((wm * 32 + mi * 16 + ra) * SWB + kk * 4 + ca));
            unsigned bfr[8][2];
#pragma unroll
            for (int nis = 0; nis < 8; nis += 2)
                ldsm4(bfr[nis][0], bfr[nis][1], bfr[nis + 1][0], bfr[nis + 1][1],
                      bbase + (uint32_t)((wn * 64 + nis * 8 + rb) * SWB + kk * 4 + cb));
#pragma unroll
            for (int mi = 0; mi < MT; mi++)
#pragma unroll
                for (int ni = 0; ni < 8; ni++)
                    mma8(acc[mi][ni], afr[mi], bfr[ni]);
        }
    }

    float mu_rs[MT][2], rstd_v[MT][2];
    if (EPI == 3) {
#pragma unroll
        for (int mi = 0; mi < MT; mi++)
#pragma unroll
            for (int h = 0; h < 2; h++) {
                int lr = wm * 32 + mi * 16 + gid + h * 8;
                float2 s0 = stats[(size_t)(m0 + lr) * 2 + 0];
                float2 s1 = stats[(size_t)(m0 + lr) * 2 + 1];
                float sum = s0.x + s1.x, ss = s0.y + s1.y;
                float mu = sum * (1.f / 512.f);
                float var = ss * (1.f / 512.f) - mu * mu;
                float rstd = rsqrtf(var + 1e-5f);
                rstd_v[mi][h] = rstd;
                mu_rs[mi][h] = mu * rstd;
            }
    }

    float rs[MT][2], rss[MT][2];
#pragma unroll
    for (int mi = 0; mi < MT; mi++) { rs[mi][0] = rs[mi][1] = 0.f; rss[mi][0] = rss[mi][1] = 0.f; }

#pragma unroll
    for (int mi = 0; mi < MT; mi++)
#pragma unroll
        for (int ni = 0; ni < 8; ni++)
#pragma unroll
            for (int e4 = 0; e4 < 4; e4++) {
                int h = e4 >> 1, e = e4 & 1;
                int col = wn * 64 + ni * 8 + q4 * 2 + e;
                float v;
                if (EPI <= 1) {
                    v = acc[mi][ni][e4] + __ldg(bias + n0 + col);
                    if (EPI == 1) { rs[mi][h] += v; rss[mi][h] += v * v; }
                } else {
                    v = rstd_v[mi][h] * acc[mi][ni][e4] - mu_rs[mi][h] * __ldg(c1 + col)
                        + __ldg(bias + col);
                }
                acc[mi][ni][e4] = v;
            }

    if (EPI == 1) {
#pragma unroll
        for (int mi = 0; mi < MT; mi++)
#pragma unroll
            for (int h = 0; h < 2; h++) {
                float s = rs[mi][h], ss = rss[mi][h];
                s  += __shfl_xor_sync(0xffffffffu, s, 1);
                s  += __shfl_xor_sync(0xffffffffu, s, 2);
                ss += __shfl_xor_sync(0xffffffffu, ss, 1);
                ss += __shfl_xor_sync(0xffffffffu, ss, 2);
                if (q4 == 0) {
                    int lr = wm * 32 + mi * 16 + gid + h * 8;
                    sred[lr * 4 + wn] = s; ssred[lr * 4 + wn] = ss;
                }
            }
        __syncthreads();
    }

#pragma unroll
    for (int mi = 0; mi < MT; mi++)
#pragma unroll
        for (int ni = 0; ni < 8; ni++) {
            int col = wn * 64 + ni * 8 + q4 * 2;
#pragma unroll
            for (int h = 0; h < 2; h++) {
                int lr = wm * 32 + mi * 16 + gid + h * 8;
                float vx = acc[mi][ni][h * 2 + 0], vy = acc[mi][ni][h * 2 + 1];
                if (EPI == 3) { vx = 1.f / (1.f + expf(-vx)); vy = 1.f / (1.f + expf(-vy)); }
                *(float2*)(out + (size_t)(m0 + lr) * OSTRIDE + n0 + col) = make_float2(vx, vy);
            }
        }
    if (EPI == 1) {
        if (tid < 64) {
            float s = 0.f, ss = 0.f;
#pragma unroll
            for (int j = 0; j < 4; j++) { s += sred[tid * 4 + j]; ss += ssred[tid * 4 + j]; }
            stats[(size_t)(m0 + tid) * 2 + blockIdx.y] = make_float2(s, ss);
        }
    }
}

// ---------------- FUSED hf MLP: z -> H (smem, XOR-swizzled) -> q -> cos-sim -> alpha ----
// All smem tiles XOR-swizzled, zero padding:
//   A-stream : 2 st x 64 m x 32 halves (64 B rows), addr ^= ((m>>1)&3)<<4
//   B-stream : 2 st x 256 n x 32 halves (64 B rows), addr ^= ((n>>1)&3)<<4
//   Hs       : 64 r x 512 halves (1024 B rows),      addr ^= (r&7)<<4
__global__ void __launch_bounds__(256, 2)
fused_hf_kernel(const __nv_bfloat16* __restrict__ Z, const __nv_bfloat16* __restrict__ W1t,
                const __nv_bfloat16* __restrict__ W2t, const float* __restrict__ b1,
                const float* __restrict__ bp, const float* __restrict__ c1,
                const float* __restrict__ prompt, float* __restrict__ alpha)
{
    constexpr int KC = 32, NIT1 = 8, NIT2 = 16, MT = 2;
    constexpr int OFF_A = 65536, OFF_B = 73728, OFF_F = 106496;

    extern __shared__ __align__(16) char dsmf[];
    __nv_bfloat16* Hs = (__nv_bfloat16*)dsmf;
    float* sred  = (float*)(dsmf + OFF_F);
    float* ssred = sred + 256;
    float* sumS  = ssred + 256;
    float* ssqS  = sumS + 64;
    float* spn   = ssqS + 64;

    int tid = threadIdx.x;
    int lane = tid & 31, warp = tid >> 5;
    int wn = warp & 3, wm = warp >> 2;
    int gid = lane >> 2, q4 = lane & 3;
    int m0 = blockIdx.x * 64;

    const __nv_bfloat16* Ab = Z + (size_t)(m0 >> 10) * (C_ * TOK_HF) + (m0 & 1023);

    if (warp == 0) {
        float s = 0.f;
        for (int i = lane; i < 256; i += 32) { float v = __ldg(prompt + i); s += v * v; }
#pragma unroll
        for (int o = 16; o; o >>= 1) s += __shfl_xor_sync(0xffffffffu, s, o);
        if (lane == 0) *spn = sqrtf(s);
    }
    if (tid < 64) { sumS[tid] = 0.f; ssqS[tid] = 0.f; }
    __syncthreads();

    uint32_t hsb    = (uint32_t)__cvta_generic_to_shared(dsmf);
    uint32_t smem_a = hsb + OFF_A;
    uint32_t smem_b = hsb + OFF_B;

    auto aAddr = [&](int st, int m, int boff) -> uint32_t {
        return smem_a + (uint32_t)((st * 64 + m) * 64) +
               (uint32_t)(boff ^ (((m >> 1) & 3) << 4));
    };
    auto bAddr = [&](int st, int n, int boff) -> uint32_t {
        return smem_b + (uint32_t)((st * 256 + n) * 64) +
               (uint32_t)(boff ^ (((n >> 1) & 3) << 4));
    };
    auto hAddr = [&](int r, int boff) -> uint32_t {
        return hsb + (uint32_t)(r * 1024) + (uint32_t)(boff ^ ((r & 7) << 4));
    };

    int la_m = tid & 63, la_kg = tid >> 6;               // 4 k-groups of 8 halves
    unsigned areg[4];
    auto load_A = [&](int k0) {
        const unsigned short* Au = (const unsigned short*)Ab;
        unsigned short hh[8];
#pragma unroll
        for (int i = 0; i < 8; i++)
            hh[i] = __ldg(Au + (size_t)(k0 + la_kg * 8 + i) * TOK_HF + la_m);
#pragma unroll
        for (int j = 0; j < 4; j++)
            areg[j] = (unsigned)hh[2 * j] | ((unsigned)hh[2 * j + 1] << 16);
    };
    auto sts_A = [&](int st) {
        int boff = (la_kg * 16) ^ (((la_m >> 1) & 3) << 4);
        *(uint4*)(dsmf + OFF_A + (st * 64 + la_m) * 64 + boff) =
            make_uint4(areg[0], areg[1], areg[2], areg[3]);
    };
    auto cp_B1 = [&](int st, int nh, int k0) {
#pragma unroll
        for (int j = 0; j < 8; j++) {
            int idx = tid + j * 256;
            int n = idx >> 3, kc = idx & 7;
            cp8(bAddr(st, n, kc * 8),
                W1t + (size_t)(nh * 256 + n) * 256 + k0 + kc * 4);
        }
        cp_commit();
    };
    auto cp_B2 = [&](int st, int k0) {
#pragma unroll
        for (int j = 0; j < 8; j++) {
            int idx = tid + j * 256;
            int n = idx >> 3, kc = idx & 7;
            cp8(bAddr(st, n, kc * 8),
                W2t + (size_t)n * 512 + k0 + kc * 4);
        }
        cp_commit();
    };

    int ra = lane & 15;
    int ca = (lane >> 4) * 16;
    int rb = (lane & 7) + ((lane >> 4) << 3);
    int cb = (lane & 8) ? 16 : 0;

    float acc[MT][8][4];

    // ================= Phase 1: H = z @ W1 + b1, two N-halves =================
#pragma unroll 1
    for (int nh = 0; nh < 2; nh++) {
#pragma unroll
        for (int mi = 0; mi < MT; mi++)
#pragma unroll
            for (int ni = 0; ni < 8; ni++)
#pragma unroll
                for (int e = 0; e < 4; e++) acc[mi][ni][e] = 0.f;

        load_A(0);
        cp_B1(0, nh, 0);
        __syncthreads();            // nh=1: protect As/Bs stage 0 from stragglers
        sts_A(0);
        load_A(KC);

        for (int it = 0; it < NIT1; it++) {
            int cur = it & 1;
            bool more = (it + 1 < NIT1);
            cp_wait<0>();
            __syncthreads();
            if (more) {
                cp_B1(cur ^ 1, nh, (it + 1) * KC);
                sts_A(cur ^ 1);
            }
            if (it + 2 < NIT1) load_A((it + 2) * KC);

#pragma unroll
            for (int kk = 0; kk < 2; kk++) {
                unsigned afr[MT][4];
#pragma unroll
                for (int mi = 0; mi < MT; mi++)
                    ldsm4(afr[mi][0], afr[mi][1], afr[mi][2], afr[mi][3],
                          aAddr(cur, wm * 32 + mi * 16 + ra, ca + kk * 32));
                unsigned bfr[8][2];
#pragma unroll
                for (int nis = 0; nis < 8; nis += 2)
                    ldsm4(bfr[nis][0], bfr[nis][1], bfr[nis + 1][0], bfr[nis + 1][1],
                          bAddr(cur, wn * 64 + nis * 8 + rb, cb + kk * 32));
#pragma unroll
                for (int mi = 0; mi < MT; mi++)
#pragma unroll
                    for (int ni = 0; ni < 8; ni++)
                        mma16(acc[mi][ni], afr[mi], bfr[ni]);
            }
        }

        // epilogue: bias, stats, store bf16 into Hs (XOR-swizzled)
        float rs[MT][2], rss[MT][2];
#pragma unroll
        for (int mi = 0; mi < MT; mi++) { rs[mi][0] = rs[mi][1] = 0.f; rss[mi][0] = rss[mi][1] = 0.f; }
#pragma unroll
        for (int mi = 0; mi < MT; mi++)
#pragma unroll
            for (int ni = 0; ni < 8; ni++)
#pragma unroll
                for (int e4 = 0; e4 < 4; e4++) {
                    int h = e4 >> 1, e = e4 & 1;
                    int col = wn * 64 + ni * 8 + q4 * 2 + e;
                    float v = acc[mi][ni][e4] + __ldg(b1 + nh * 256 + col);
                    rs[mi][h] += v; rss[mi][h] += v * v;
                    acc[mi][ni][e4] = v;
                }
#pragma unroll
        for (int mi = 0; mi < MT; mi++)
#pragma unroll
            for (int h = 0; h < 2; h++) {
                float s = rs[mi][h], ss = rss[mi][h];
                s  += __shfl_xor_sync(0xffffffffu, s, 1);
                s  += __shfl_xor_sync(0xffffffffu, s, 2);
                ss += __shfl_xor_sync(0xffffffffu, ss, 1);
                ss += __shfl_xor_sync(0xffffffffu, ss, 2);
                if (q4 == 0) {
                    int lr = wm * 32 + mi * 16 + gid + h * 8;
                    sred[lr * 4 + wn] = s; ssred[lr * 4 + wn] = ss;
                }
            }
        __syncthreads();
        if (tid < 64) {
            float s = 0.f, ss = 0.f;
#pragma unroll
            for (int j = 0; j < 4; j++) { s += sred[tid * 4 + j]; ss += ssred[tid * 4 + j]; }
            sumS[tid] += s; ssqS[tid] += ss;
        }
#pragma unroll
        for (int mi = 0; mi < MT; mi++)
#pragma unroll
            for (int ni = 0; ni < 8; ni++) {
                int col = wn * 64 + ni * 8 + q4 * 2;
#pragma unroll
                for (int h = 0; h < 2; h++) {
                    int lr = wm * 32 + mi * 16 + gid + h * 8;
                    int boff = ((nh * 256 + col) * 2) ^ ((lr & 7) << 4);
                    *(__nv_bfloat162*)(dsmf + lr * 1024 + boff) =
                        __floats2bfloat162_rn(acc[mi][ni][h * 2 + 0], acc[mi][ni][h * 2 + 1]);
                }
            }
    }

    // ================= Phase 2: q = H @ W2' (A from Hs), LN-fold, cos-sim =================
#pragma unroll
    for (int mi = 0; mi < MT; mi++)
#pragma unroll
        for (int ni = 0; ni < 8; ni++)
#pragma unroll
            for (int e = 0; e < 4; e++) acc[mi][ni][e] = 0.f;

    cp_B2(0, 0);
    for (int it = 0; it < NIT2; it++) {
        int cur = it & 1;
        bool more = (it + 1 < NIT2);
        cp_wait<0>();
        __syncthreads();                      // it=0 also publishes Hs stores
        if (more) cp_B2(cur ^ 1, (it + 1) * KC);

#pragma unroll
        for (int kk = 0; kk < 2; kk++) {
            unsigned afr[MT][4];
#pragma unroll
            for (int mi = 0; mi < MT; mi++)
                ldsm4(afr[mi][0], afr[mi][1], afr[mi][2], afr[mi][3],
                      hAddr(wm * 32 + mi * 16 + ra, it * 64 + kk * 32 + ca));
            unsigned bfr[8][2];
#pragma unroll
            for (int nis = 0; nis < 8; nis += 2)
                ldsm4(bfr[nis][0], bfr[nis][1], bfr[nis + 1][0], bfr[nis + 1][1],
                      bAddr(cur, wn * 64 + nis * 8 + rb, cb + kk * 32));
#pragma unroll
            for (int mi = 0; mi < MT; mi++)
#pragma unroll
                for (int ni = 0; ni < 8; ni++)
                    mma16(acc[mi][ni], afr[mi], bfr[ni]);
        }
    }

    // epilogue: LN-fold + cos-sim
    float mu_rs[MT][2], rstd_v[MT][2];
#pragma unroll
    for (int mi = 0; mi < MT; mi++)
#pragma unroll
        for (int h = 0; h < 2; h++) {
            int lr = wm * 32 + mi * 16 + gid + h * 8;
            float sum = sumS[lr], ss = ssqS[lr];
            float mu = sum * (1.f / 512.f);
            float var = ss * (1.f / 512.f) - mu * mu;
            float rstd = rsqrtf(var + 1e-5f);
            rstd_v[mi][h] = rstd;
            mu_rs[mi][h] = mu * rstd;
        }

    float rs[MT][2], rss[MT][2];
#pragma unroll
    for (int mi = 0; mi < MT; mi++) { rs[mi][0] = rs[mi][1] = 0.f; rss[mi][0] = rss[mi][1] = 0.f; }
#pragma unroll
    for (int mi = 0; mi < MT; mi++)
#pragma unroll
        for (int ni = 0; ni < 8; ni++)
#pragma unroll
            for (int e4 = 0; e4 < 4; e4++) {
                int h = e4 >> 1, e = e4 & 1;
                int col = wn * 64 + ni * 8 + q4 * 2 + e;
                float v = rstd_v[mi][h] * acc[mi][ni][e4] - mu_rs[mi][h] * __ldg(c1 + col)
                          + __ldg(bp + col);
                rs[mi][h] += v * __ldg(prompt + col);
                rss[mi][h] += v * v;
            }
#pragma unroll
    for (int mi = 0; mi < MT; mi++)
#pragma unroll
        for (int h = 0; h < 2; h++) {
            float s = rs[mi][h], ss = rss[mi][h];
            s  += __shfl_xor_sync(0xffffffffu, s, 1);
            s  += __shfl_xor_sync(0xffffffffu, s, 2);
            ss += __shfl_xor_sync(0xffffffffu, ss, 1);
            ss += __shfl_xor_sync(0xffffffffu, ss, 2);
            if (q4 == 0) {
                int lr = wm * 32 + mi * 16 + gid + h * 8;
                sred[lr * 4 + wn] = s; ssred[lr * 4 + wn] = ss;
            }
        }
    __syncthreads();
    if (tid < 64) {
        float dot = 0.f, nsq = 0.f;
#pragma unroll
        for (int j = 0; j < 4; j++) { dot += sred[tid * 4 + j]; nsq += ssred[tid * 4 + j]; }
        float sim = dot / (fmaxf(sqrtf(nsq), 1e-8f) * fmaxf(*spn, 1e-8f));
        alpha[m0 + tid] = fmaxf(sim, 0.f);
    }
}

// ---------------- K5: apply alpha/gate, inverse Haar, write output ----------------
__global__ void final_kernel(const float* __restrict__ xb, float* __restrict__ out)
{
    __shared__ __align__(16) float xs[8 * 128];
    int bi = blockIdx.x, c = blockIdx.y, b = blockIdx.z;
    size_t img = ((size_t)(b * C_ + c)) * H_;
    int t = threadIdx.x;
    int lrow = t >> 5, lcol = t & 31;
    ((float4*)xs)[t] = ((const float4*)(xb + (img + 8 * bi + lrow) * W_))[lcol];
    __syncthreads();
    int rp = t >> 6, j = t & 63;
    float2 top = ((const float2*)(xs + (2 * rp) * W_))[j];
    float2 bot = ((const float2*)(xs + (2 * rp + 1) * W_))[j];
    float p00 = top.x, p01 = top.y, p10 = bot.x, p11 = bot.y;
    float a  = 0.25f * (p00 + p01 + p10 + p11);
    float hb = 0.25f * (p00 - p01 + p10 - p11);
    float vb = 0.25f * (p00 + p01 - p10 - p11);
    float db = 0.25f * (p00 - p01 - p10 + p11);
    int hr = 4 * bi + rp, hc = j;
    int tok = (hr >> 1) * 32 + (hc >> 1);
    float ah = __ldg(&g_alpha[(0 * B_ + b) * TOK_HF + tok]);
    float av = __ldg(&g_alpha[(1 * B_ + b) * TOK_HF + tok]);
    float ad = __ldg(&g_alpha[(2 * B_ + b) * TOK_HF + tok]);
    int tg = (hr >> 2) * 16 + (hc >> 2);
    float gt = __ldg(&g_gate[((size_t)(b * 256 + tg)) * C_ + c]);
    float ae = a * gt, he = hb * ah, ve = vb * av, de = db * ad;
    float2 o0 = make_float2(ae + he + ve + de, ae - he + ve - de);
    float2 o1 = make_float2(ae + he - ve - de, ae - he - ve + de);
    int row0 = 8 * bi + 2 * rp;
    ((float2*)(out + (img + row0) * W_))[j] = o0;
    ((float2*)(out + (img + row0 + 1) * W_))[j] = o1;
}

static constexpr int SMEM_G = (2 * 64 * 36 + 2 * 256 * 36 + 512 + 4) * 4;   // ~92 KB
static constexpr int SMEM_F = 106496 + (256 + 256 + 64 + 64 + 1) * 4;       // 109060 B

extern "C" void kernel_launch(void* const* d_in, const int* in_sizes, int n_in,
                              void* d_out, int out_size)
{
    const float* xb      = (const float*)d_in[0];
    const float* xsm     = (const float*)d_in[1];
    const float* hf_w1   = (const float*)d_in[2];
    const float* hf_b1   = (const float*)d_in[3];
    const float* hf_ln_w = (const float*)d_in[4];
    const float* hf_ln_b = (const float*)d_in[5];
    const float* hf_w2   = (const float*)d_in[6];
    const float* hf_b2   = (const float*)d_in[7];
    const float* hf_pr   = (const float*)d_in[8];
    const float* low_w   = (const float*)d_in[9];
    const float* low_b   = (const float*)d_in[10];
    const float* lf_w1   = (const float*)d_in[11];
    const float* lf_b1   = (const float*)d_in[12];
    const float* lf_ln_w = (const float*)d_in[13];
    const float* lf_ln_b = (const float*)d_in[14];
    const float* lf_w2   = (const float*)d_in[15];
    const float* lf_b2   = (const float*)d_in[16];

    void *pz, *pps, *pHlf, *pktok, *pgate, *palpha, *pwt, *pwth, *psl, *pc1, *pbp;
    cudaGetSymbolAddress(&pz, g_z);
    cudaGetSymbolAddress(&pps, g_ps);
    cudaGetSymbolAddress(&pHlf, g_Hlf);
    cudaGetSymbolAddress(&pktok, g_ktok);
    cudaGetSymbolAddress(&pgate, g_gate);
    cudaGetSymbolAddress(&palpha, g_alpha);
    cudaGetSymbolAddress(&pwt, g_wt);
    cudaGetSymbolAddress(&pwth, g_wth);
    cudaGetSymbolAddress(&psl, g_stats_lf);
    cudaGetSymbolAddress(&pc1, g_c1);
    cudaGetSymbolAddress(&pbp, g_bp);
    const float* wt = (const float*)pwt;
    const __nv_bfloat16* wth = (const __nv_bfloat16*)pwth;
    float2* sl = (float2*)psl;
    const float* c1 = (const float*)pc1;
    const float* bp = (const float*)pbp;

    cudaFuncSetAttribute((const void*)fused_hf_kernel,
                         cudaFuncAttributeMaxDynamicSharedMemorySize, SMEM_F);
    cudaFuncSetAttribute((const void*)gemm256_kernel<512, 1, 0, 256>,
                         cudaFuncAttributeMaxDynamicSharedMemorySize, SMEM_G);
    cudaFuncSetAttribute((const void*)gemm256_kernel<256, 2, 1, 512>,
                         cudaFuncAttributeMaxDynamicSharedMemorySize, SMEM_G);
    cudaFuncSetAttribute((const void*)gemm256_kernel<512, 2, 3, 256>,
                         cudaFuncAttributeMaxDynamicSharedMemorySize, SMEM_G);

    // Order: fused_hf is the 4th launch (ncu profiles it).
    transpose5_kernel<<<dim3(16, 16, 5), dim3(32, 8)>>>(hf_w1, hf_w2, low_w, lf_w1, lf_w2,
                                                        hf_ln_w, lf_ln_w);
    haar_z_kernel<<<dim3(4, 256, 16), 256>>>(xb);
    fold_kernel<<<2, 256>>>(hf_w2, hf_ln_b, hf_b2, lf_w2, lf_ln_b, lf_b2);

    fused_hf_kernel<<<M_HF / 64, 256, SMEM_F>>>(
        (const __nv_bfloat16*)pz, wth, wth + 512 * 256, hf_b1, bp + 0, c1 + 0, hf_pr,
        (float*)palpha);

    pool_small_kernel<<<dim3(512, 16), 256>>>(xsm);

    // lf chain (tf32, unchanged)
    gemm256_kernel<512, 1, 0, 256><<<dim3(M_LF / 64, 1), 256, SMEM_G>>>(
        (const float*)pps, wt + 2 * 512 * 256, low_b, nullptr, (float*)pktok, nullptr, nullptr);
    gemm256_kernel<256, 2, 1, 512><<<dim3(M_LF / 64, 2), 256, SMEM_G>>>(
        (const float*)pktok, wt + 3 * 512 * 256, lf_b1, nullptr, (float*)pHlf, sl, nullptr);
    gemm256_kernel<512, 2, 3, 256><<<dim3(M_LF / 64, 1), 256, SMEM_G>>>(
        (const float*)pHlf, wt + 4 * 512 * 256, bp + 256, nullptr, (float*)pgate, sl, c1 + 256);

    final_kernel<<<dim3(16, 256, 16), 256>>>(xb, (float*)d_out);
}

// round 14
// speedup vs baseline: 1.0377x; 1.0377x over previous
#include <cuda_runtime.h>
#include <cuda_bf16.h>
#include <cstdint>
#include <math.h>

#define DEV_INLINE __device__ __forceinline__

static constexpr int B_ = 16, C_ = 256, H_ = 128, W_ = 128;
static constexpr int CS = 512;
static constexpr int TOK_HF = 1024;
static constexpr int M_HF = 3 * B_ * TOK_HF;     // 49152
static constexpr int M_LF = B_ * 256;            // 4096

// ---------------- scratch ----------------
__device__ __nv_bfloat16 g_z[3ULL * B_ * C_ * TOK_HF];   // [band][b][c][tok] bf16
__device__ float g_ps[(size_t)B_ * CS * 256];            // [b][s][tok]
__device__ __nv_bfloat16 g_Hh[(size_t)M_HF * 512];       // RAW hidden (hf) bf16
__device__ float g_Hlf[(size_t)M_LF * 512];              // RAW hidden (lf) fp32
__device__ float g_ktok[(size_t)M_LF * C_];
__device__ float g_gate[(size_t)M_LF * C_];
__device__ float g_alpha[3 * B_ * TOK_HF];
__device__ float g_wt[5ULL * 512 * 256];                 // transposed weights [n][k] fp32
__device__ __nv_bfloat16 g_wth[2ULL * 512 * 256];        // bf16: [0]=hf_w1t(512n,256k), [1]=hf_w2t'(256n,512k)
__device__ float2 g_stats_hf[(size_t)M_HF * 2];
__device__ float2 g_stats_lf[(size_t)M_LF * 2];
__device__ float g_c1[2 * 256];
__device__ float g_bp[2 * 256];

// ---------------- weight transpose (+ LN-weight folding + bf16 copies) ----------------
__global__ void transpose5_kernel(const float* __restrict__ w0, const float* __restrict__ w1,
                                  const float* __restrict__ w2, const float* __restrict__ w3,
                                  const float* __restrict__ w4,
                                  const float* __restrict__ hf_lnw, const float* __restrict__ lf_lnw)
{
    __shared__ float tile[32][33];
    int mi = blockIdx.z;
    const float* in; int R, Cc; const float* lnw = nullptr;
    switch (mi) {
        case 0: in = w0; R = 256; Cc = 512; break;                 // hf_w1 -> [512n][256k]
        case 1: in = w1; R = 512; Cc = 256; lnw = hf_lnw; break;   // hf_w2' -> [256n][512k]
        case 2: in = w2; R = 512; Cc = 256; break;
        case 3: in = w3; R = 256; Cc = 512; break;
        default: in = w4; R = 512; Cc = 256; lnw = lf_lnw; break;
    }
    float* out = g_wt + (size_t)mi * 512 * 256;
    int bx = blockIdx.x * 32, by = blockIdx.y * 32;
    if (bx >= Cc || by >= R) return;
    int tx = threadIdx.x, ty = threadIdx.y;
#pragma unroll
    for (int j = 0; j < 32; j += 8) {
        int row = by + ty + j;
        float v = in[(size_t)row * Cc + bx + tx];
        if (lnw) v *= __ldg(lnw + row);
        tile[ty + j][tx] = v;
    }
    __syncthreads();
#pragma unroll
    for (int j = 0; j < 32; j += 8) {
        float v = tile[tx][ty + j];
        size_t oidx = (size_t)(bx + ty + j) * R + by + tx;
        out[oidx] = v;
        if (mi == 0) g_wth[oidx] = __float2bfloat16(v);
        if (mi == 1) g_wth[512 * 256 + oidx] = __float2bfloat16(v);
    }
}

// fold: c1[n]=col-sums of W2'; bp[n]=b2[n]+lnb@W2
__global__ void fold_kernel(const float* __restrict__ w2a, const float* __restrict__ lnba,
                            const float* __restrict__ b2a,
                            const float* __restrict__ w2b, const float* __restrict__ lnbb,
                            const float* __restrict__ b2b)
{
    int mi = blockIdx.x;
    int n = threadIdx.x;
    const float* wt = g_wt + (size_t)(mi ? 4 : 1) * 512 * 256;
    const float* w2 = mi ? w2b : w2a;
    const float* lnb = mi ? lnbb : lnba;
    const float* b2 = mi ? b2b : b2a;
    float s1 = 0.f, s2 = 0.f;
    for (int k = 0; k < 512; k++) {
        s1 += wt[(size_t)n * 512 + k];
        s2 += lnb[k] * w2[(size_t)k * 256 + n];
    }
    g_c1[mi * 256 + n] = s1;
    g_bp[mi * 256 + n] = b2[n] + s2;
}

// ---------------- K1: Haar bands -> abs-pooled z tokens (bf16 out) ----------------
__global__ void haar_z_kernel(const float* __restrict__ xb)
{
    int tid = threadIdx.x;
    int tk = blockIdx.x * 256 + tid;
    int c = blockIdx.y, b = blockIdx.z;
    int ti = tk >> 5, tj = tk & 31;
    const float* base = xb + ((size_t)(b * C_ + c) * H_ + 4 * ti) * W_ + 4 * tj;
    float4 r0 = *(const float4*)(base);
    float4 r1 = *(const float4*)(base + W_);
    float4 r2 = *(const float4*)(base + 2 * W_);
    float4 r3 = *(const float4*)(base + 3 * W_);
    float zh = 0.f, zv = 0.f, zd = 0.f;
#define HBLK(p00, p01, p10, p11) \
    zh += fabsf((p00) - (p01) + (p10) - (p11)); \
    zv += fabsf((p00) + (p01) - (p10) - (p11)); \
    zd += fabsf((p00) - (p01) - (p10) + (p11));
    HBLK(r0.x, r0.y, r1.x, r1.y)
    HBLK(r0.z, r0.w, r1.z, r1.w)
    HBLK(r2.x, r2.y, r3.x, r3.y)
    HBLK(r2.z, r2.w, r3.z, r3.w)
#undef HBLK
    const float s = 0.0625f;
    size_t base_o = ((size_t)(b) * C_ + c) * TOK_HF + tk;
    const size_t BS = (size_t)B_ * C_ * TOK_HF;
    g_z[base_o]          = __float2bfloat16(zh * s);
    g_z[BS + base_o]     = __float2bfloat16(zv * s);
    g_z[2 * BS + base_o] = __float2bfloat16(zd * s);
}

// ---------------- K2: 4x4 mean-pool of x_small ----------------
__global__ void pool_small_kernel(const float* __restrict__ xsm)
{
    int s = blockIdx.x, b = blockIdx.y;
    const float* src = xsm + ((size_t)(b * CS + s)) * 64 * 64;
    int t = threadIdx.x;
    int tj = t & 15, ti = t >> 4;
    float sum = 0.f;
#pragma unroll
    for (int r = 0; r < 4; r++) {
        float4 v = *(const float4*)(src + (4 * ti + r) * 64 + 4 * tj);
        sum += v.x + v.y + v.z + v.w;
    }
    g_ps[((size_t)(b * CS + s)) * 256 + t] = sum * (1.f / 16.f);
}

// ---------------- asm helpers ----------------
DEV_INLINE void mma8(float* c, const unsigned* a, const unsigned* b) {
    asm volatile("mma.sync.aligned.m16n8k8.row.col.f32.tf32.tf32.f32 "
                 "{%0,%1,%2,%3}, {%4,%5,%6,%7}, {%8,%9}, {%0,%1,%2,%3};"
                 : "+f"(c[0]), "+f"(c[1]), "+f"(c[2]), "+f"(c[3])
                 : "r"(a[0]), "r"(a[1]), "r"(a[2]), "r"(a[3]),
                   "r"(b[0]), "r"(b[1]));
}
DEV_INLINE void mma16(float* c, const unsigned* a, const unsigned* b) {
    asm volatile("mma.sync.aligned.m16n8k16.row.col.f32.bf16.bf16.f32 "
                 "{%0,%1,%2,%3}, {%4,%5,%6,%7}, {%8,%9}, {%0,%1,%2,%3};"
                 : "+f"(c[0]), "+f"(c[1]), "+f"(c[2]), "+f"(c[3])
                 : "r"(a[0]), "r"(a[1]), "r"(a[2]), "r"(a[3]),
                   "r"(b[0]), "r"(b[1]));
}
DEV_INLINE void ldsm4(unsigned& r0, unsigned& r1, unsigned& r2, unsigned& r3, uint32_t addr) {
    asm volatile("ldmatrix.sync.aligned.m8n8.x4.shared.b16 {%0,%1,%2,%3}, [%4];"
                 : "=r"(r0), "=r"(r1), "=r"(r2), "=r"(r3) : "r"(addr));
}
DEV_INLINE void ldsm4t(unsigned& r0, unsigned& r1, unsigned& r2, unsigned& r3, uint32_t addr) {
    asm volatile("ldmatrix.sync.aligned.m8n8.x4.trans.shared.b16 {%0,%1,%2,%3}, [%4];"
                 : "=r"(r0), "=r"(r1), "=r"(r2), "=r"(r3) : "r"(addr));
}
DEV_INLINE void cp16(uint32_t s, const void* g) {
    asm volatile("cp.async.cg.shared.global [%0], [%1], 16;" :: "r"(s), "l"(g));
}
DEV_INLINE void cp_commit() { asm volatile("cp.async.commit_group;"); }
template<int NN> DEV_INLINE void cp_wait() { asm volatile("cp.async.wait_group %0;" :: "n"(NN)); }

// ---------------- tf32 64x256-tile GEMM (R6-proven, lf chain) ----------------
template<int K, int AMODE, int EPI, int OSTRIDE>
__global__ void __launch_bounds__(256, 2)
gemm256_kernel(const float* __restrict__ A, const float* __restrict__ Bt,
               const float* __restrict__ bias, const float* __restrict__ p0,
               float* __restrict__ out, float2* __restrict__ stats,
               const float* __restrict__ c1)
{
    constexpr int KC = 32, SW = 36, SWB = SW * 4, NIT = K / KC, NN = 256;
    constexpr int MT = 2;

    extern __shared__ __align__(16) float dsm[];
    float* As = dsm;
    float* Bs = As + 2 * 64 * SW;
    float* sred = Bs + 2 * NN * SW;
    float* ssred = sred + 256;

    int tid = threadIdx.x;
    int lane = tid & 31, warp = tid >> 5;
    int wn = warp & 3, wm = warp >> 2;
    int gid = lane >> 2, q4 = lane & 3;
    int m0 = blockIdx.x * 64;
    int n0 = blockIdx.y * 256;

    const float* Ab; int astride = 0;
    if (AMODE == 1) { Ab = A + (size_t)(m0 >> 8) * (CS * 256) + (m0 & 255); astride = 256; }
    else { Ab = A + (size_t)m0 * K; }
    const float* BtB = Bt + (size_t)n0 * K;

    uint32_t smem_a = (uint32_t)__cvta_generic_to_shared(As);
    uint32_t smem_b = (uint32_t)__cvta_generic_to_shared(Bs);

    int la_m = tid & 63, la_kg = tid >> 6;
    float areg[8];
    auto load_A = [&](int k0) {
        if (AMODE == 1) {
#pragma unroll
            for (int i = 0; i < 8; i++)
                areg[i] = __ldg(Ab + (size_t)(k0 + la_kg * 8 + i) * astride + la_m);
        }
    };
    auto sts_A = [&](int st) {
        if (AMODE == 1) {
            float* p = As + st * 64 * SW + la_m * SW + la_kg * 8;
            *(float4*)(p)     = make_float4(areg[0], areg[1], areg[2], areg[3]);
            *(float4*)(p + 4) = make_float4(areg[4], areg[5], areg[6], areg[7]);
        }
    };
    auto cp_stage = [&](int st, int k0) {
        if (AMODE == 2) {
#pragma unroll
            for (int j = 0; j < 2; j++) {
                int idx = tid + j * 256;
                int m = idx >> 3, kq = idx & 7;
                cp16(smem_a + (uint32_t)((st * 64 + m) * SW + kq * 4) * 4,
                     Ab + (size_t)m * K + k0 + kq * 4);
            }
        }
#pragma unroll
        for (int j = 0; j < 8; j++) {
            int idx = tid + j * 256;
            int n = idx >> 3, kc = idx & 7;
            cp16(smem_b + (uint32_t)((st * NN + n) * SW + kc * 4) * 4,
                 BtB + (size_t)n * K + k0 + kc * 4);
        }
        cp_commit();
    };

    int ra = lane & 15;
    int ca = (lane & 16) ? 16 : 0;
    int rb = (lane & 7) + ((lane >> 4) << 3);
    int cb = (lane & 8) ? 16 : 0;

    float acc[MT][8][4];
#pragma unroll
    for (int mi = 0; mi < MT; mi++)
#pragma unroll
        for (int ni = 0; ni < 8; ni++)
#pragma unroll
            for (int e = 0; e < 4; e++) acc[mi][ni][e] = 0.f;

    load_A(0);
    cp_stage(0, 0);
    sts_A(0);
    if (NIT > 1) load_A(KC);

    for (int it = 0; it < NIT; it++) {
        int cur = it & 1;
        bool more = (it + 1 < NIT);
        cp_wait<0>();
        __syncthreads();
        if (more) {
            cp_stage(cur ^ 1, (it + 1) * KC);
            sts_A(cur ^ 1);
        }
        if (it + 2 < NIT) load_A((it + 2) * KC);

        uint32_t abase = smem_a + (uint32_t)(cur * 64 * SW) * 4;
        uint32_t bbase = smem_b + (uint32_t)(cur * NN * SW) * 4;
#pragma unroll
        for (int kk = 0; kk < KC; kk += 8) {
            unsigned afr[MT][4];
#pragma unroll
            for (int mi = 0; mi < MT; mi++)
                ldsm4(afr[mi][0], afr[mi][1], afr[mi][2], afr[mi][3],
                      abase + (uint32_t)((wm * 32 + mi * 16 + ra) * SWB + kk * 4 + ca));
            unsigned bfr[8][2];
#pragma unroll
            for (int nis = 0; nis < 8; nis += 2)
                ldsm4(bfr[nis][0], bfr[nis][1], bfr[nis + 1][0], bfr[nis + 1][1],
                      bbase + (uint32_t)((wn * 64 + nis * 8 + rb) * SWB + kk * 4 + cb));
#pragma unroll
            for (int mi = 0; mi < MT; mi++)
#pragma unroll
                for (int ni = 0; ni < 8; ni++)
                    mma8(acc[mi][ni], afr[mi], bfr[ni]);
        }
    }

    float mu_rs[MT][2], rstd_v[MT][2];
    if (EPI == 3) {
#pragma unroll
        for (int mi = 0; mi < MT; mi++)
#pragma unroll
            for (int h = 0; h < 2; h++) {
                int lr = wm * 32 + mi * 16 + gid + h * 8;
                float2 s0 = stats[(size_t)(m0 + lr) * 2 + 0];
                float2 s1 = stats[(size_t)(m0 + lr) * 2 + 1];
                float sum = s0.x + s1.x, ss = s0.y + s1.y;
                float mu = sum * (1.f / 512.f);
                float var = ss * (1.f / 512.f) - mu * mu;
                float rstd = rsqrtf(var + 1e-5f);
                rstd_v[mi][h] = rstd;
                mu_rs[mi][h] = mu * rstd;
            }
    }

    float rs[MT][2], rss[MT][2];
#pragma unroll
    for (int mi = 0; mi < MT; mi++) { rs[mi][0] = rs[mi][1] = 0.f; rss[mi][0] = rss[mi][1] = 0.f; }

#pragma unroll
    for (int mi = 0; mi < MT; mi++)
#pragma unroll
        for (int ni = 0; ni < 8; ni++)
#pragma unroll
            for (int e4 = 0; e4 < 4; e4++) {
                int h = e4 >> 1, e = e4 & 1;
                int col = wn * 64 + ni * 8 + q4 * 2 + e;
                float v;
                if (EPI <= 1) {
                    v = acc[mi][ni][e4] + __ldg(bias + n0 + col);
                    if (EPI == 1) { rs[mi][h] += v; rss[mi][h] += v * v; }
                } else {
                    v = rstd_v[mi][h] * acc[mi][ni][e4] - mu_rs[mi][h] * __ldg(c1 + col)
                        + __ldg(bias + col);
                }
                acc[mi][ni][e4] = v;
            }

    if (EPI == 1) {
#pragma unroll
        for (int mi = 0; mi < MT; mi++)
#pragma unroll
            for (int h = 0; h < 2; h++) {
                float s = rs[mi][h], ss = rss[mi][h];
                s  += __shfl_xor_sync(0xffffffffu, s, 1);
                s  += __shfl_xor_sync(0xffffffffu, s, 2);
                ss += __shfl_xor_sync(0xffffffffu, ss, 1);
                ss += __shfl_xor_sync(0xffffffffu, ss, 2);
                if (q4 == 0) {
                    int lr = wm * 32 + mi * 16 + gid + h * 8;
                    sred[lr * 4 + wn] = s; ssred[lr * 4 + wn] = ss;
                }
            }
        __syncthreads();
    }

#pragma unroll
    for (int mi = 0; mi < MT; mi++)
#pragma unroll
        for (int ni = 0; ni < 8; ni++) {
            int col = wn * 64 + ni * 8 + q4 * 2;
#pragma unroll
            for (int h = 0; h < 2; h++) {
                int lr = wm * 32 + mi * 16 + gid + h * 8;
                float vx = acc[mi][ni][h * 2 + 0], vy = acc[mi][ni][h * 2 + 1];
                if (EPI == 3) { vx = 1.f / (1.f + expf(-vx)); vy = 1.f / (1.f + expf(-vy)); }
                *(float2*)(out + (size_t)(m0 + lr) * OSTRIDE + n0 + col) = make_float2(vx, vy);
            }
        }
    if (EPI == 1) {
        if (tid < 64) {
            float s = 0.f, ss = 0.f;
#pragma unroll
            for (int j = 0; j < 4; j++) { s += sred[tid * 4 + j]; ss += ssred[tid * 4 + j]; }
            stats[(size_t)(m0 + tid) * 2 + blockIdx.y] = make_float2(s, ss);
        }
    }
}

// ---------------- bf16 GEMM1-hf with cp.async A + ldmatrix.trans ----------------
// A = z tile, loaded as [k][m] (m contiguous in gmem) via cp16, fragments via trans.
// C = A @ W1t^T + b1; stores bf16 H + partial row stats.
__global__ void __launch_bounds__(256, 2)
gemmz_kernel(const __nv_bfloat16* __restrict__ Z, const __nv_bfloat16* __restrict__ Bt,
             const float* __restrict__ bias, __nv_bfloat16* __restrict__ outH,
             float2* __restrict__ stats)
{
    constexpr int KC = 64, NIT = 256 / KC;   // 4
    constexpr int SWBH = 72;                 // B row stride in halves (144 B)
    constexpr int MT = 2;

    extern __shared__ __align__(16) char dsmz[];
    __nv_bfloat16* As = (__nv_bfloat16*)dsmz;            // 2 st x 64 k x 64 m (128 B rows)
    __nv_bfloat16* Bs = As + 2 * 64 * 64;                // 2 st x 256 n x 72
    float* sred = (float*)(Bs + 2 * 256 * SWBH);
    float* ssred = sred + 256;

    int tid = threadIdx.x;
    int lane = tid & 31, warp = tid >> 5;
    int wn = warp & 3, wm = warp >> 2;
    int gid = lane >> 2, q4 = lane & 3;
    int m0 = blockIdx.x * 64;
    int n0 = blockIdx.y * 256;

    const __nv_bfloat16* Ab = Z + (size_t)(m0 >> 10) * (C_ * TOK_HF) + (m0 & 1023);
    const __nv_bfloat16* BtB = Bt + (size_t)n0 * 256;

    uint32_t smem_a = (uint32_t)__cvta_generic_to_shared(As);
    uint32_t smem_b = (uint32_t)__cvta_generic_to_shared(Bs);

    auto cp_stage = [&](int st, int k0) {
        // A: 64 k-rows x 128 B, XOR swizzle by (k&7)<<4
#pragma unroll
        for (int j = 0; j < 2; j++) {
            int idx = tid + j * 256;
            int k = idx >> 3, mc = idx & 7;
            cp16(smem_a + (uint32_t)((st * 64 + k) * 128 + ((mc * 16) ^ ((k & 7) << 4))),
                 Ab + (size_t)(k0 + k) * TOK_HF + mc * 8);
        }
        // B: 256 n-rows x 64 halves (8 chunks of 16 B), padded 144 B rows
#pragma unroll
        for (int j = 0; j < 8; j++) {
            int idx = tid + j * 256;
            int n = idx >> 3, kc = idx & 7;
            cp16(smem_b + (uint32_t)((st * 256 + n) * SWBH + kc * 8) * 2,
                 BtB + (size_t)n * 256 + k0 + kc * 8);
        }
        cp_commit();
    };

    // trans-A lane mapping: a0..a3 = (m0-7,k0-7),(m8-15,k0-7),(m0-7,k8-15),(m8-15,k8-15)
    int ksrc = (lane & 7) + ((lane >> 4) << 3);        // 0..15 within k16 step
    int moff = ((lane >> 3) & 1) << 3;                 // 0 or 8
    int rb = (lane & 7) + ((lane >> 4) << 3);
    int cb = (lane & 8) ? 16 : 0;

    float acc[MT][8][4];
#pragma unroll
    for (int mi = 0; mi < MT; mi++)
#pragma unroll
        for (int ni = 0; ni < 8; ni++)
#pragma unroll
            for (int e = 0; e < 4; e++) acc[mi][ni][e] = 0.f;

    cp_stage(0, 0);

    for (int it = 0; it < NIT; it++) {
        int cur = it & 1;
        bool more = (it + 1 < NIT);
        cp_wait<0>();
        __syncthreads();
        if (more) cp_stage(cur ^ 1, (it + 1) * KC);

        uint32_t abase = smem_a + (uint32_t)(cur * 64 * 128);
        uint32_t bbase = smem_b + (uint32_t)(cur * 256 * SWBH) * 2;
#pragma unroll
        for (int kk = 0; kk < 4; kk++) {               // four k16 steps
            int krow = kk * 16 + ksrc;
            unsigned afr[MT][4];
#pragma unroll
            for (int mi = 0; mi < MT; mi++) {
                int mb = (wm * 32 + mi * 16 + moff) * 2;
                ldsm4t(afr[mi][0], afr[mi][1], afr[mi][2], afr[mi][3],
                       abase + (uint32_t)(krow * 128 + (mb ^ ((ksrc & 7) << 4))));
            }
            unsigned bfr[8][2];
#pragma unroll
            for (int nis = 0; nis < 8; nis += 2)
                ldsm4(bfr[nis][0], bfr[nis][1], bfr[nis + 1][0], bfr[nis + 1][1],
                      bbase + (uint32_t)((wn * 64 + nis * 8 + rb) * (SWBH * 2) + cb + kk * 32));
#pragma unroll
            for (int mi = 0; mi < MT; mi++)
#pragma unroll
                for (int ni = 0; ni < 8; ni++)
                    mma16(acc[mi][ni], afr[mi], bfr[ni]);
        }
    }

    // ---- epilogue: bias + partial row stats + bf16 H store ----
    float rs[MT][2], rss[MT][2];
#pragma unroll
    for (int mi = 0; mi < MT; mi++) { rs[mi][0] = rs[mi][1] = 0.f; rss[mi][0] = rss[mi][1] = 0.f; }
#pragma unroll
    for (int mi = 0; mi < MT; mi++)
#pragma unroll
        for (int ni = 0; ni < 8; ni++)
#pragma unroll
            for (int e4 = 0; e4 < 4; e4++) {
                int h = e4 >> 1, e = e4 & 1;
                int col = wn * 64 + ni * 8 + q4 * 2 + e;
                float v = acc[mi][ni][e4] + __ldg(bias + n0 + col);
                rs[mi][h] += v; rss[mi][h] += v * v;
                acc[mi][ni][e4] = v;
            }
#pragma unroll
    for (int mi = 0; mi < MT; mi++)
#pragma unroll
        for (int h = 0; h < 2; h++) {
            float s = rs[mi][h], ss = rss[mi][h];
            s  += __shfl_xor_sync(0xffffffffu, s, 1);
            s  += __shfl_xor_sync(0xffffffffu, s, 2);
            ss += __shfl_xor_sync(0xffffffffu, ss, 1);
            ss += __shfl_xor_sync(0xffffffffu, ss, 2);
            if (q4 == 0) {
                int lr = wm * 32 + mi * 16 + gid + h * 8;
                sred[lr * 4 + wn] = s; ssred[lr * 4 + wn] = ss;
            }
        }
    __syncthreads();
#pragma unroll
    for (int mi = 0; mi < MT; mi++)
#pragma unroll
        for (int ni = 0; ni < 8; ni++) {
            int col = wn * 64 + ni * 8 + q4 * 2;
#pragma unroll
            for (int h = 0; h < 2; h++) {
                int lr = wm * 32 + mi * 16 + gid + h * 8;
                *(__nv_bfloat162*)(outH + (size_t)(m0 + lr) * 512 + n0 + col) =
                    __floats2bfloat162_rn(acc[mi][ni][h * 2 + 0], acc[mi][ni][h * 2 + 1]);
            }
        }
    if (tid < 64) {
        float s = 0.f, ss = 0.f;
#pragma unroll
        for (int j = 0; j < 4; j++) { s += sred[tid * 4 + j]; ss += ssred[tid * 4 + j]; }
        stats[(size_t)(m0 + tid) * 2 + blockIdx.y] = make_float2(s, ss);
    }
}

// ---------------- bf16 64x256-tile GEMM, KC=64 (hf GEMM2, R11-proven) ----------------
__global__ void __launch_bounds__(256, 2)
gemmh2_kernel(const __nv_bfloat16* __restrict__ A, const __nv_bfloat16* __restrict__ Bt,
              const float* __restrict__ bias, const float* __restrict__ p0,
              float* __restrict__ outv, float2* __restrict__ stats,
              const float* __restrict__ c1)
{
    constexpr int K = 512, KC = 64, SW = 72, SWB = SW * 2, NIT = K / KC, NN = 256;
    constexpr int MT = 2;

    extern __shared__ __align__(16) char dsmh[];
    __nv_bfloat16* As = (__nv_bfloat16*)dsmh;
    __nv_bfloat16* Bs = As + 2 * 64 * SW;
    float* sred = (float*)(Bs + 2 * NN * SW);
    float* ssred = sred + 256;
    float* spn = ssred + 256;

    int tid = threadIdx.x;
    int lane = tid & 31, warp = tid >> 5;
    int wn = warp & 3, wm = warp >> 2;
    int gid = lane >> 2, q4 = lane & 3;
    int m0 = blockIdx.x * 64;

    const __nv_bfloat16* Ab = A + (size_t)m0 * K;
    const __nv_bfloat16* BtB = Bt;

    if (warp == 0) {
        float s = 0.f;
        for (int i = lane; i < 256; i += 32) { float v = __ldg(p0 + i); s += v * v; }
#pragma unroll
        for (int o = 16; o; o >>= 1) s += __shfl_xor_sync(0xffffffffu, s, o);
        if (lane == 0) *spn = sqrtf(s);
    }

    uint32_t smem_a = (uint32_t)__cvta_generic_to_shared(As);
    uint32_t smem_b = (uint32_t)__cvta_generic_to_shared(Bs);

    auto cp_stage = [&](int st, int k0) {
#pragma unroll
        for (int j = 0; j < 2; j++) {
            int idx = tid + j * 256;
            int m = idx >> 3, kq = idx & 7;
            cp16(smem_a + (uint32_t)((st * 64 + m) * SW + kq * 8) * 2,
                 Ab + (size_t)m * K + k0 + kq * 8);
        }
#pragma unroll
        for (int j = 0; j < 8; j++) {
            int idx = tid + j * 256;
            int n = idx >> 3, kc = idx & 7;
            cp16(smem_b + (uint32_t)((st * NN + n) * SW + kc * 8) * 2,
                 BtB + (size_t)n * K + k0 + kc * 8);
        }
        cp_commit();
    };

    int ra = lane & 15;
    int ca = (lane >> 4) * 16;
    int rb = (lane & 7) + ((lane >> 4) << 3);
    int cb = (lane & 8) ? 16 : 0;

    float acc[MT][8][4];
#pragma unroll
    for (int mi = 0; mi < MT; mi++)
#pragma unroll
        for (int ni = 0; ni < 8; ni++)
#pragma unroll
            for (int e = 0; e < 4; e++) acc[mi][ni][e] = 0.f;

    cp_stage(0, 0);

    for (int it = 0; it < NIT; it++) {
        int cur = it & 1;
        bool more = (it + 1 < NIT);
        cp_wait<0>();
        __syncthreads();
        if (more) cp_stage(cur ^ 1, (it + 1) * KC);

        uint32_t abase = smem_a + (uint32_t)(cur * 64 * SW) * 2;
        uint32_t bbase = smem_b + (uint32_t)(cur * NN * SW) * 2;
#pragma unroll
        for (int kk = 0; kk < 4; kk++) {
            unsigned afr[MT][4];
#pragma unroll
            for (int mi = 0; mi < MT; mi++)
                ldsm4(afr[mi][0], afr[mi][1], afr[mi][2], afr[mi][3],
                      abase + (uint32_t)((wm * 32 + mi * 16 + ra) * SWB + ca + kk * 32));
            unsigned bfr[8][2];
#pragma unroll
            for (int nis = 0; nis < 8; nis += 2)
                ldsm4(bfr[nis][0], bfr[nis][1], bfr[nis + 1][0], bfr[nis + 1][1],
                      bbase + (uint32_t)((wn * 64 + nis * 8 + rb) * SWB + cb + kk * 32));
#pragma unroll
            for (int mi = 0; mi < MT; mi++)
#pragma unroll
                for (int ni = 0; ni < 8; ni++)
                    mma16(acc[mi][ni], afr[mi], bfr[ni]);
        }
    }

    float mu_rs[MT][2], rstd_v[MT][2];
#pragma unroll
    for (int mi = 0; mi < MT; mi++)
#pragma unroll
        for (int h = 0; h < 2; h++) {
            int lr = wm * 32 + mi * 16 + gid + h * 8;
            float2 s0 = stats[(size_t)(m0 + lr) * 2 + 0];
            float2 s1 = stats[(size_t)(m0 + lr) * 2 + 1];
            float sum = s0.x + s1.x, ss = s0.y + s1.y;
            float mu = sum * (1.f / 512.f);
            float var = ss * (1.f / 512.f) - mu * mu;
            float rstd = rsqrtf(var + 1e-5f);
            rstd_v[mi][h] = rstd;
            mu_rs[mi][h] = mu * rstd;
        }

    float rs[MT][2], rss[MT][2];
#pragma unroll
    for (int mi = 0; mi < MT; mi++) { rs[mi][0] = rs[mi][1] = 0.f; rss[mi][0] = rss[mi][1] = 0.f; }
#pragma unroll
    for (int mi = 0; mi < MT; mi++)
#pragma unroll
        for (int ni = 0; ni < 8; ni++)
#pragma unroll
            for (int e4 = 0; e4 < 4; e4++) {
                int h = e4 >> 1, e = e4 & 1;
                int col = wn * 64 + ni * 8 + q4 * 2 + e;
                float v = rstd_v[mi][h] * acc[mi][ni][e4] - mu_rs[mi][h] * __ldg(c1 + col)
                          + __ldg(bias + col);
                rs[mi][h] += v * __ldg(p0 + col);
                rss[mi][h] += v * v;
            }
#pragma unroll
    for (int mi = 0; mi < MT; mi++)
#pragma unroll
        for (int h = 0; h < 2; h++) {
            float s = rs[mi][h], ss = rss[mi][h];
            s  += __shfl_xor_sync(0xffffffffu, s, 1);
            s  += __shfl_xor_sync(0xffffffffu, s, 2);
            ss += __shfl_xor_sync(0xffffffffu, ss, 1);
            ss += __shfl_xor_sync(0xffffffffu, ss, 2);
            if (q4 == 0) {
                int lr = wm * 32 + mi * 16 + gid + h * 8;
                sred[lr * 4 + wn] = s; ssred[lr * 4 + wn] = ss;
            }
        }
    __syncthreads();
    if (tid < 64) {
        float dot = 0.f, nsq = 0.f;
#pragma unroll
        for (int j = 0; j < 4; j++) { dot += sred[tid * 4 + j]; nsq += ssred[tid * 4 + j]; }
        float nq = sqrtf(nsq);
        float sim = dot / (fmaxf(nq, 1e-8f) * fmaxf(*spn, 1e-8f));
        outv[m0 + tid] = fmaxf(sim, 0.f);
    }
}

// ---------------- K5: apply alpha/gate, inverse Haar, write output ----------------
__global__ void final_kernel(const float* __restrict__ xb, float* __restrict__ out)
{
    __shared__ __align__(16) float xs[8 * 128];
    int bi = blockIdx.x, c = blockIdx.y, b = blockIdx.z;
    size_t img = ((size_t)(b * C_ + c)) * H_;
    int t = threadIdx.x;
    int lrow = t >> 5, lcol = t & 31;
    ((float4*)xs)[t] = ((const float4*)(xb + (img + 8 * bi + lrow) * W_))[lcol];
    __syncthreads();
    int rp = t >> 6, j = t & 63;
    float2 top = ((const float2*)(xs + (2 * rp) * W_))[j];
    float2 bot = ((const float2*)(xs + (2 * rp + 1) * W_))[j];
    float p00 = top.x, p01 = top.y, p10 = bot.x, p11 = bot.y;
    float a  = 0.25f * (p00 + p01 + p10 + p11);
    float hb = 0.25f * (p00 - p01 + p10 - p11);
    float vb = 0.25f * (p00 + p01 - p10 - p11);
    float db = 0.25f * (p00 - p01 - p10 + p11);
    int hr = 4 * bi + rp, hc = j;
    int tok = (hr >> 1) * 32 + (hc >> 1);
    float ah = __ldg(&g_alpha[(0 * B_ + b) * TOK_HF + tok]);
    float av = __ldg(&g_alpha[(1 * B_ + b) * TOK_HF + tok]);
    float ad = __ldg(&g_alpha[(2 * B_ + b) * TOK_HF + tok]);
    int tg = (hr >> 2) * 16 + (hc >> 2);
    float gt = __ldg(&g_gate[((size_t)(b * 256 + tg)) * C_ + c]);
    float ae = a * gt, he = hb * ah, ve = vb * av, de = db * ad;
    float2 o0 = make_float2(ae + he + ve + de, ae - he + ve - de);
    float2 o1 = make_float2(ae + he - ve - de, ae - he - ve + de);
    int row0 = 8 * bi + 2 * rp;
    ((float2*)(out + (img + row0) * W_))[j] = o0;
    ((float2*)(out + (img + row0 + 1) * W_))[j] = o1;
}

static constexpr int SMEM_G = (2 * 64 * 36 + 2 * 256 * 36 + 512 + 4) * 4;       // ~92 KB
static constexpr int SMEM_Z = (2 * 64 * 64 + 2 * 256 * 72) * 2 + 512 * 4;       // ~92 KB
static constexpr int SMEM_H2 = (2 * 64 * 72 + 2 * 256 * 72) * 2 + (512 + 4) * 4; // ~92 KB

extern "C" void kernel_launch(void* const* d_in, const int* in_sizes, int n_in,
                              void* d_out, int out_size)
{
    const float* xb      = (const float*)d_in[0];
    const float* xsm     = (const float*)d_in[1];
    const float* hf_w1   = (const float*)d_in[2];
    const float* hf_b1   = (const float*)d_in[3];
    const float* hf_ln_w = (const float*)d_in[4];
    const float* hf_ln_b = (const float*)d_in[5];
    const float* hf_w2   = (const float*)d_in[6];
    const float* hf_b2   = (const float*)d_in[7];
    const float* hf_pr   = (const float*)d_in[8];
    const float* low_w   = (const float*)d_in[9];
    const float* low_b   = (const float*)d_in[10];
    const float* lf_w1   = (const float*)d_in[11];
    const float* lf_b1   = (const float*)d_in[12];
    const float* lf_ln_w = (const float*)d_in[13];
    const float* lf_ln_b = (const float*)d_in[14];
    const float* lf_w2   = (const float*)d_in[15];
    const float* lf_b2   = (const float*)d_in[16];

    void *pz, *pps, *pHh, *pHlf, *pktok, *pgate, *palpha, *pwt, *pwth, *psh, *psl, *pc1, *pbp;
    cudaGetSymbolAddress(&pz, g_z);
    cudaGetSymbolAddress(&pps, g_ps);
    cudaGetSymbolAddress(&pHh, g_Hh);
    cudaGetSymbolAddress(&pHlf, g_Hlf);
    cudaGetSymbolAddress(&pktok, g_ktok);
    cudaGetSymbolAddress(&pgate, g_gate);
    cudaGetSymbolAddress(&palpha, g_alpha);
    cudaGetSymbolAddress(&pwt, g_wt);
    cudaGetSymbolAddress(&pwth, g_wth);
    cudaGetSymbolAddress(&psh, g_stats_hf);
    cudaGetSymbolAddress(&psl, g_stats_lf);
    cudaGetSymbolAddress(&pc1, g_c1);
    cudaGetSymbolAddress(&pbp, g_bp);
    const float* wt = (const float*)pwt;
    const __nv_bfloat16* wth = (const __nv_bfloat16*)pwth;
    float2* sh = (float2*)psh;
    float2* sl = (float2*)psl;
    const float* c1 = (const float*)pc1;
    const float* bp = (const float*)pbp;

    cudaFuncSetAttribute((const void*)gemmz_kernel,
                         cudaFuncAttributeMaxDynamicSharedMemorySize, SMEM_Z);
    cudaFuncSetAttribute((const void*)gemmh2_kernel,
                         cudaFuncAttributeMaxDynamicSharedMemorySize, SMEM_H2);
    cudaFuncSetAttribute((const void*)gemm256_kernel<512, 1, 0, 256>,
                         cudaFuncAttributeMaxDynamicSharedMemorySize, SMEM_G);
    cudaFuncSetAttribute((const void*)gemm256_kernel<256, 2, 1, 512>,
                         cudaFuncAttributeMaxDynamicSharedMemorySize, SMEM_G);
    cudaFuncSetAttribute((const void*)gemm256_kernel<512, 2, 3, 256>,
                         cudaFuncAttributeMaxDynamicSharedMemorySize, SMEM_G);

    // Order: gemmz is the 4th launch (ncu profiles it).
    transpose5_kernel<<<dim3(16, 16, 5), dim3(32, 8)>>>(hf_w1, hf_w2, low_w, lf_w1, lf_w2,
                                                        hf_ln_w, lf_ln_w);
    haar_z_kernel<<<dim3(4, 256, 16), 256>>>(xb);
    fold_kernel<<<2, 256>>>(hf_w2, hf_ln_b, hf_b2, lf_w2, lf_ln_b, lf_b2);

    // hf chain
    gemmz_kernel<<<dim3(M_HF / 64, 2), 256, SMEM_Z>>>(
        (const __nv_bfloat16*)pz, wth, hf_b1, (__nv_bfloat16*)pHh, sh);
    pool_small_kernel<<<dim3(512, 16), 256>>>(xsm);
    gemmh2_kernel<<<M_HF / 64, 256, SMEM_H2>>>(
        (const __nv_bfloat16*)pHh, wth + 512 * 256, bp + 0, hf_pr, (float*)palpha, sh, c1 + 0);

    // lf chain (tf32, unchanged)
    gemm256_kernel<512, 1, 0, 256><<<dim3(M_LF / 64, 1), 256, SMEM_G>>>(
        (const float*)pps, wt + 2 * 512 * 256, low_b, nullptr, (float*)pktok, nullptr, nullptr);
    gemm256_kernel<256, 2, 1, 512><<<dim3(M_LF / 64, 2), 256, SMEM_G>>>(
        (const float*)pktok, wt + 3 * 512 * 256, lf_b1, nullptr, (float*)pHlf, sl, nullptr);
    gemm256_kernel<512, 2, 3, 256><<<dim3(M_LF / 64, 1), 256, SMEM_G>>>(
        (const float*)pHlf, wt + 4 * 512 * 256, bp + 256, nullptr, (float*)pgate, sl, c1 + 256);

    final_kernel<<<dim3(16, 256, 16), 256>>>(xb, (float*)d_out);
}

// round 15
// speedup vs baseline: 1.1031x; 1.0630x over previous
#include <cuda_runtime.h>
#include <cuda_bf16.h>
#include <cstdint>
#include <math.h>

#define DEV_INLINE __device__ __forceinline__

static constexpr int B_ = 16, C_ = 256, H_ = 128, W_ = 128;
static constexpr int CS = 512;
static constexpr int TOK_HF = 1024;
static constexpr int M_HF = 3 * B_ * TOK_HF;     // 49152
static constexpr int M_LF = B_ * 256;            // 4096

// ---------------- scratch ----------------
__device__ __nv_bfloat16 g_z[3ULL * B_ * C_ * TOK_HF];   // [band][b][c][tok] bf16
__device__ float g_ps[(size_t)B_ * CS * 256];            // [b][s][tok]
__device__ __nv_bfloat16 g_Hh[(size_t)M_HF * 512];       // RAW hidden (hf) bf16
__device__ float g_Hlf[(size_t)M_LF * 512];              // RAW hidden (lf) fp32
__device__ float g_ktok[(size_t)M_LF * C_];
__device__ float g_gate[(size_t)M_LF * C_];
__device__ float g_alpha[3 * B_ * TOK_HF];
__device__ float g_wt[5ULL * 512 * 256];                 // transposed weights [n][k] fp32
__device__ __nv_bfloat16 g_wth[2ULL * 512 * 256];        // bf16: [0]=hf_w1t, [1]=hf_w2t'
__device__ float2 g_stats_hf[(size_t)M_HF * 2];
__device__ float2 g_stats_lf[(size_t)M_LF * 4];          // 4 N-slots now
__device__ float g_c1[2 * 256];
__device__ float g_bp[2 * 256];

// ---------------- weight transpose (+ LN-weight folding + bf16 copies) ----------------
__global__ void transpose5_kernel(const float* __restrict__ w0, const float* __restrict__ w1,
                                  const float* __restrict__ w2, const float* __restrict__ w3,
                                  const float* __restrict__ w4,
                                  const float* __restrict__ hf_lnw, const float* __restrict__ lf_lnw)
{
    __shared__ float tile[32][33];
    int mi = blockIdx.z;
    const float* in; int R, Cc; const float* lnw = nullptr;
    switch (mi) {
        case 0: in = w0; R = 256; Cc = 512; break;
        case 1: in = w1; R = 512; Cc = 256; lnw = hf_lnw; break;
        case 2: in = w2; R = 512; Cc = 256; break;
        case 3: in = w3; R = 256; Cc = 512; break;
        default: in = w4; R = 512; Cc = 256; lnw = lf_lnw; break;
    }
    float* out = g_wt + (size_t)mi * 512 * 256;
    int bx = blockIdx.x * 32, by = blockIdx.y * 32;
    if (bx >= Cc || by >= R) return;
    int tx = threadIdx.x, ty = threadIdx.y;
#pragma unroll
    for (int j = 0; j < 32; j += 8) {
        int row = by + ty + j;
        float v = in[(size_t)row * Cc + bx + tx];
        if (lnw) v *= __ldg(lnw + row);
        tile[ty + j][tx] = v;
    }
    __syncthreads();
#pragma unroll
    for (int j = 0; j < 32; j += 8) {
        float v = tile[tx][ty + j];
        size_t oidx = (size_t)(bx + ty + j) * R + by + tx;
        out[oidx] = v;
        if (mi == 0) g_wth[oidx] = __float2bfloat16(v);
        if (mi == 1) g_wth[512 * 256 + oidx] = __float2bfloat16(v);
    }
}

__global__ void fold_kernel(const float* __restrict__ w2a, const float* __restrict__ lnba,
                            const float* __restrict__ b2a,
                            const float* __restrict__ w2b, const float* __restrict__ lnbb,
                            const float* __restrict__ b2b)
{
    int mi = blockIdx.x;
    int n = threadIdx.x;
    const float* wt = g_wt + (size_t)(mi ? 4 : 1) * 512 * 256;
    const float* w2 = mi ? w2b : w2a;
    const float* lnb = mi ? lnbb : lnba;
    const float* b2 = mi ? b2b : b2a;
    float s1 = 0.f, s2 = 0.f;
    for (int k = 0; k < 512; k++) {
        s1 += wt[(size_t)n * 512 + k];
        s2 += lnb[k] * w2[(size_t)k * 256 + n];
    }
    g_c1[mi * 256 + n] = s1;
    g_bp[mi * 256 + n] = b2[n] + s2;
}

// ---------------- K1: Haar bands -> abs-pooled z tokens (bf16 out) ----------------
__global__ void haar_z_kernel(const float* __restrict__ xb)
{
    int tid = threadIdx.x;
    int tk = blockIdx.x * 256 + tid;
    int c = blockIdx.y, b = blockIdx.z;
    int ti = tk >> 5, tj = tk & 31;
    const float* base = xb + ((size_t)(b * C_ + c) * H_ + 4 * ti) * W_ + 4 * tj;
    float4 r0 = *(const float4*)(base);
    float4 r1 = *(const float4*)(base + W_);
    float4 r2 = *(const float4*)(base + 2 * W_);
    float4 r3 = *(const float4*)(base + 3 * W_);
    float zh = 0.f, zv = 0.f, zd = 0.f;
#define HBLK(p00, p01, p10, p11) \
    zh += fabsf((p00) - (p01) + (p10) - (p11)); \
    zv += fabsf((p00) + (p01) - (p10) - (p11)); \
    zd += fabsf((p00) - (p01) - (p10) + (p11));
    HBLK(r0.x, r0.y, r1.x, r1.y)
    HBLK(r0.z, r0.w, r1.z, r1.w)
    HBLK(r2.x, r2.y, r3.x, r3.y)
    HBLK(r2.z, r2.w, r3.z, r3.w)
#undef HBLK
    const float s = 0.0625f;
    size_t base_o = ((size_t)(b) * C_ + c) * TOK_HF + tk;
    const size_t BS = (size_t)B_ * C_ * TOK_HF;
    g_z[base_o]          = __float2bfloat16(zh * s);
    g_z[BS + base_o]     = __float2bfloat16(zv * s);
    g_z[2 * BS + base_o] = __float2bfloat16(zd * s);
}

// ---------------- K2: 4x4 mean-pool of x_small ----------------
__global__ void pool_small_kernel(const float* __restrict__ xsm)
{
    int s = blockIdx.x, b = blockIdx.y;
    const float* src = xsm + ((size_t)(b * CS + s)) * 64 * 64;
    int t = threadIdx.x;
    int tj = t & 15, ti = t >> 4;
    float sum = 0.f;
#pragma unroll
    for (int r = 0; r < 4; r++) {
        float4 v = *(const float4*)(src + (4 * ti + r) * 64 + 4 * tj);
        sum += v.x + v.y + v.z + v.w;
    }
    g_ps[((size_t)(b * CS + s)) * 256 + t] = sum * (1.f / 16.f);
}

// ---------------- asm helpers ----------------
DEV_INLINE void mma8(float* c, const unsigned* a, const unsigned* b) {
    asm volatile("mma.sync.aligned.m16n8k8.row.col.f32.tf32.tf32.f32 "
                 "{%0,%1,%2,%3}, {%4,%5,%6,%7}, {%8,%9}, {%0,%1,%2,%3};"
                 : "+f"(c[0]), "+f"(c[1]), "+f"(c[2]), "+f"(c[3])
                 : "r"(a[0]), "r"(a[1]), "r"(a[2]), "r"(a[3]),
                   "r"(b[0]), "r"(b[1]));
}
DEV_INLINE void mma16(float* c, const unsigned* a, const unsigned* b) {
    asm volatile("mma.sync.aligned.m16n8k16.row.col.f32.bf16.bf16.f32 "
                 "{%0,%1,%2,%3}, {%4,%5,%6,%7}, {%8,%9}, {%0,%1,%2,%3};"
                 : "+f"(c[0]), "+f"(c[1]), "+f"(c[2]), "+f"(c[3])
                 : "r"(a[0]), "r"(a[1]), "r"(a[2]), "r"(a[3]),
                   "r"(b[0]), "r"(b[1]));
}
DEV_INLINE void ldsm4(unsigned& r0, unsigned& r1, unsigned& r2, unsigned& r3, uint32_t addr) {
    asm volatile("ldmatrix.sync.aligned.m8n8.x4.shared.b16 {%0,%1,%2,%3}, [%4];"
                 : "=r"(r0), "=r"(r1), "=r"(r2), "=r"(r3) : "r"(addr));
}
DEV_INLINE void ldsm4t(unsigned& r0, unsigned& r1, unsigned& r2, unsigned& r3, uint32_t addr) {
    asm volatile("ldmatrix.sync.aligned.m8n8.x4.trans.shared.b16 {%0,%1,%2,%3}, [%4];"
                 : "=r"(r0), "=r"(r1), "=r"(r2), "=r"(r3) : "r"(addr));
}
DEV_INLINE void cp16(uint32_t s, const void* g) {
    asm volatile("cp.async.cg.shared.global [%0], [%1], 16;" :: "r"(s), "l"(g));
}
DEV_INLINE void cp_commit() { asm volatile("cp.async.commit_group;"); }
template<int NN> DEV_INLINE void cp_wait() { asm volatile("cp.async.wait_group %0;" :: "n"(NN)); }

// ---------------- tf32 64xNN-tile GEMM, generic NN/KC (lf chain) ----------------
// EPI: 0 = +bias store; 1 = +bias store + row stats slot blockIdx.y (NST slots);
//      3 = LN-fold(NST slots) + sigmoid store.
template<int K, int AMODE, int EPI, int OSTRIDE, int NN, int KC, int NST>
__global__ void __launch_bounds__(256, 2)
gemm256_kernel(const float* __restrict__ A, const float* __restrict__ Bt,
               const float* __restrict__ bias, float* __restrict__ out,
               float2* __restrict__ stats, const float* __restrict__ c1)
{
    constexpr int SW = KC + 4, SWB = SW * 4, NIT = K / KC;
    constexpr int MT = 2, NT = NN / 32;          // n-tiles per warp
    constexpr int CPR = KC / 4;                  // 16B chunks per row

    extern __shared__ __align__(16) float dsm[];
    float* As = dsm;                             // 2 * 64 * SW
    float* Bs = As + 2 * 64 * SW;                // 2 * NN * SW
    float* sred = Bs + 2 * NN * SW;
    float* ssred = sred + 256;

    int tid = threadIdx.x;
    int lane = tid & 31, warp = tid >> 5;
    int wn = warp & 3, wm = warp >> 2;
    int gid = lane >> 2, q4 = lane & 3;
    int m0 = blockIdx.x * 64;
    int n0 = blockIdx.y * NN;

    const float* Ab; int astride = 0;
    if (AMODE == 1) { Ab = A + (size_t)(m0 >> 8) * (CS * 256) + (m0 & 255); astride = 256; }
    else { Ab = A + (size_t)m0 * K; }
    const float* BtB = Bt + (size_t)n0 * K;

    uint32_t smem_a = (uint32_t)__cvta_generic_to_shared(As);
    uint32_t smem_b = (uint32_t)__cvta_generic_to_shared(Bs);

    int la_m = tid & 63, la_kg = tid >> 6;       // 4 k-groups of KC/4 values
    float areg[CPR];
    auto load_A = [&](int k0) {
        if (AMODE == 1) {
#pragma unroll
            for (int i = 0; i < CPR; i++)
                areg[i] = __ldg(Ab + (size_t)(k0 + la_kg * CPR + i) * astride + la_m);
        }
    };
    auto sts_A = [&](int st) {
        if (AMODE == 1) {
            float* p = As + st * 64 * SW + la_m * SW + la_kg * CPR;
#pragma unroll
            for (int i = 0; i < CPR; i += 4)
                *(float4*)(p + i) = make_float4(areg[i], areg[i + 1], areg[i + 2], areg[i + 3]);
        }
    };
    auto cp_stage = [&](int st, int k0) {
        if (AMODE == 2) {
#pragma unroll
            for (int j = 0; j < 64 * CPR / 256; j++) {
                int idx = tid + j * 256;
                int m = idx / CPR, kq = idx % CPR;
                cp16(smem_a + (uint32_t)((st * 64 + m) * SW + kq * 4) * 4,
                     Ab + (size_t)m * K + k0 + kq * 4);
            }
        }
#pragma unroll
        for (int j = 0; j < NN * CPR / 256; j++) {
            int idx = tid + j * 256;
            int n = idx / CPR, kc = idx % CPR;
            cp16(smem_b + (uint32_t)((st * NN + n) * SW + kc * 4) * 4,
                 BtB + (size_t)n * K + k0 + kc * 4);
        }
        cp_commit();
    };

    int ra = lane & 15;
    int ca = (lane & 16) ? 16 : 0;
    int rb = (lane & 7) + ((lane >> 4) << 3);
    int cb = (lane & 8) ? 16 : 0;

    float acc[MT][NT][4];
#pragma unroll
    for (int mi = 0; mi < MT; mi++)
#pragma unroll
        for (int ni = 0; ni < NT; ni++)
#pragma unroll
            for (int e = 0; e < 4; e++) acc[mi][ni][e] = 0.f;

    load_A(0);
    cp_stage(0, 0);
    sts_A(0);
    if (NIT > 1) load_A(KC);

    for (int it = 0; it < NIT; it++) {
        int cur = it & 1;
        bool more = (it + 1 < NIT);
        cp_wait<0>();
        __syncthreads();
        if (more) {
            cp_stage(cur ^ 1, (it + 1) * KC);
            sts_A(cur ^ 1);
        }
        if (it + 2 < NIT) load_A((it + 2) * KC);

        uint32_t abase = smem_a + (uint32_t)(cur * 64 * SW) * 4;
        uint32_t bbase = smem_b + (uint32_t)(cur * NN * SW) * 4;
#pragma unroll
        for (int kk = 0; kk < KC; kk += 8) {
            unsigned afr[MT][4];
#pragma unroll
            for (int mi = 0; mi < MT; mi++)
                ldsm4(afr[mi][0], afr[mi][1], afr[mi][2], afr[mi][3],
                      abase + (uint32_t)((wm * 32 + mi * 16 + ra) * SWB + kk * 4 + ca));
            unsigned bfr[NT][2];
#pragma unroll
            for (int nis = 0; nis < NT; nis += 2)
                ldsm4(bfr[nis][0], bfr[nis][1], bfr[nis + 1][0], bfr[nis + 1][1],
                      bbase + (uint32_t)((wn * (NN / 4) + nis * 8 + rb) * SWB + kk * 4 + cb));
#pragma unroll
            for (int mi = 0; mi < MT; mi++)
#pragma unroll
                for (int ni = 0; ni < NT; ni++)
                    mma8(acc[mi][ni], afr[mi], bfr[ni]);
        }
    }

    float mu_rs[MT][2], rstd_v[MT][2];
    if (EPI == 3) {
#pragma unroll
        for (int mi = 0; mi < MT; mi++)
#pragma unroll
            for (int h = 0; h < 2; h++) {
                int lr = wm * 32 + mi * 16 + gid + h * 8;
                float sum = 0.f, ss = 0.f;
#pragma unroll
                for (int j = 0; j < NST; j++) {
                    float2 s = stats[(size_t)(m0 + lr) * NST + j];
                    sum += s.x; ss += s.y;
                }
                float mu = sum * (1.f / 512.f);
                float var = ss * (1.f / 512.f) - mu * mu;
                float rstd = rsqrtf(var + 1e-5f);
                rstd_v[mi][h] = rstd;
                mu_rs[mi][h] = mu * rstd;
            }
    }

    float rs[MT][2], rss[MT][2];
#pragma unroll
    for (int mi = 0; mi < MT; mi++) { rs[mi][0] = rs[mi][1] = 0.f; rss[mi][0] = rss[mi][1] = 0.f; }

#pragma unroll
    for (int mi = 0; mi < MT; mi++)
#pragma unroll
        for (int ni = 0; ni < NT; ni++)
#pragma unroll
            for (int e4 = 0; e4 < 4; e4++) {
                int h = e4 >> 1, e = e4 & 1;
                int col = wn * (NN / 4) + ni * 8 + q4 * 2 + e;
                float v;
                if (EPI <= 1) {
                    v = acc[mi][ni][e4] + __ldg(bias + n0 + col);
                    if (EPI == 1) { rs[mi][h] += v; rss[mi][h] += v * v; }
                } else {
                    v = rstd_v[mi][h] * acc[mi][ni][e4] - mu_rs[mi][h] * __ldg(c1 + n0 + col)
                        + __ldg(bias + n0 + col);
                }
                acc[mi][ni][e4] = v;
            }

    if (EPI == 1) {
#pragma unroll
        for (int mi = 0; mi < MT; mi++)
#pragma unroll
            for (int h = 0; h < 2; h++) {
                float s = rs[mi][h], ss = rss[mi][h];
                s  += __shfl_xor_sync(0xffffffffu, s, 1);
                s  += __shfl_xor_sync(0xffffffffu, s, 2);
                ss += __shfl_xor_sync(0xffffffffu, ss, 1);
                ss += __shfl_xor_sync(0xffffffffu, ss, 2);
                if (q4 == 0) {
                    int lr = wm * 32 + mi * 16 + gid + h * 8;
                    sred[lr * 4 + wn] = s; ssred[lr * 4 + wn] = ss;
                }
            }
        __syncthreads();
    }

#pragma unroll
    for (int mi = 0; mi < MT; mi++)
#pragma unroll
        for (int ni = 0; ni < NT; ni++) {
            int col = wn * (NN / 4) + ni * 8 + q4 * 2;
#pragma unroll
            for (int h = 0; h < 2; h++) {
                int lr = wm * 32 + mi * 16 + gid + h * 8;
                float vx = acc[mi][ni][h * 2 + 0], vy = acc[mi][ni][h * 2 + 1];
                if (EPI == 3) { vx = 1.f / (1.f + expf(-vx)); vy = 1.f / (1.f + expf(-vy)); }
                *(float2*)(out + (size_t)(m0 + lr) * OSTRIDE + n0 + col) = make_float2(vx, vy);
            }
        }
    if (EPI == 1) {
        if (tid < 64) {
            float s = 0.f, ss = 0.f;
#pragma unroll
            for (int j = 0; j < 4; j++) { s += sred[tid * 4 + j]; ss += ssred[tid * 4 + j]; }
            stats[(size_t)(m0 + tid) * NST + blockIdx.y] = make_float2(s, ss);
        }
    }
}

// ---------------- bf16 GEMM1-hf with cp.async A + ldmatrix.trans (R14-proven) ----------------
__global__ void __launch_bounds__(256, 2)
gemmz_kernel(const __nv_bfloat16* __restrict__ Z, const __nv_bfloat16* __restrict__ Bt,
             const float* __restrict__ bias, __nv_bfloat16* __restrict__ outH,
             float2* __restrict__ stats)
{
    constexpr int KC = 64, NIT = 256 / KC;
    constexpr int SWBH = 72;
    constexpr int MT = 2;

    extern __shared__ __align__(16) char dsmz[];
    __nv_bfloat16* As = (__nv_bfloat16*)dsmz;
    __nv_bfloat16* Bs = As + 2 * 64 * 64;
    float* sred = (float*)(Bs + 2 * 256 * SWBH);
    float* ssred = sred + 256;

    int tid = threadIdx.x;
    int lane = tid & 31, warp = tid >> 5;
    int wn = warp & 3, wm = warp >> 2;
    int gid = lane >> 2, q4 = lane & 3;
    int m0 = blockIdx.x * 64;
    int n0 = blockIdx.y * 256;

    const __nv_bfloat16* Ab = Z + (size_t)(m0 >> 10) * (C_ * TOK_HF) + (m0 & 1023);
    const __nv_bfloat16* BtB = Bt + (size_t)n0 * 256;

    uint32_t smem_a = (uint32_t)__cvta_generic_to_shared(As);
    uint32_t smem_b = (uint32_t)__cvta_generic_to_shared(Bs);

    auto cp_stage = [&](int st, int k0) {
#pragma unroll
        for (int j = 0; j < 2; j++) {
            int idx = tid + j * 256;
            int k = idx >> 3, mc = idx & 7;
            cp16(smem_a + (uint32_t)((st * 64 + k) * 128 + ((mc * 16) ^ ((k & 7) << 4))),
                 Ab + (size_t)(k0 + k) * TOK_HF + mc * 8);
        }
#pragma unroll
        for (int j = 0; j < 8; j++) {
            int idx = tid + j * 256;
            int n = idx >> 3, kc = idx & 7;
            cp16(smem_b + (uint32_t)((st * 256 + n) * SWBH + kc * 8) * 2,
                 BtB + (size_t)n * 256 + k0 + kc * 8);
        }
        cp_commit();
    };

    int ksrc = (lane & 7) + ((lane >> 4) << 3);
    int moff = ((lane >> 3) & 1) << 3;
    int rb = (lane & 7) + ((lane >> 4) << 3);
    int cb = (lane & 8) ? 16 : 0;

    float acc[MT][8][4];
#pragma unroll
    for (int mi = 0; mi < MT; mi++)
#pragma unroll
        for (int ni = 0; ni < 8; ni++)
#pragma unroll
            for (int e = 0; e < 4; e++) acc[mi][ni][e] = 0.f;

    cp_stage(0, 0);

    for (int it = 0; it < NIT; it++) {
        int cur = it & 1;
        bool more = (it + 1 < NIT);
        cp_wait<0>();
        __syncthreads();
        if (more) cp_stage(cur ^ 1, (it + 1) * KC);

        uint32_t abase = smem_a + (uint32_t)(cur * 64 * 128);
        uint32_t bbase = smem_b + (uint32_t)(cur * 256 * SWBH) * 2;
#pragma unroll
        for (int kk = 0; kk < 4; kk++) {
            int krow = kk * 16 + ksrc;
            unsigned afr[MT][4];
#pragma unroll
            for (int mi = 0; mi < MT; mi++) {
                int mb = (wm * 32 + mi * 16 + moff) * 2;
                ldsm4t(afr[mi][0], afr[mi][1], afr[mi][2], afr[mi][3],
                       abase + (uint32_t)(krow * 128 + (mb ^ ((ksrc & 7) << 4))));
            }
            unsigned bfr[8][2];
#pragma unroll
            for (int nis = 0; nis < 8; nis += 2)
                ldsm4(bfr[nis][0], bfr[nis][1], bfr[nis + 1][0], bfr[nis + 1][1],
                      bbase + (uint32_t)((wn * 64 + nis * 8 + rb) * (SWBH * 2) + cb + kk * 32));
#pragma unroll
            for (int mi = 0; mi < MT; mi++)
#pragma unroll
                for (int ni = 0; ni < 8; ni++)
                    mma16(acc[mi][ni], afr[mi], bfr[ni]);
        }
    }

    float rs[MT][2], rss[MT][2];
#pragma unroll
    for (int mi = 0; mi < MT; mi++) { rs[mi][0] = rs[mi][1] = 0.f; rss[mi][0] = rss[mi][1] = 0.f; }
#pragma unroll
    for (int mi = 0; mi < MT; mi++)
#pragma unroll
        for (int ni = 0; ni < 8; ni++)
#pragma unroll
            for (int e4 = 0; e4 < 4; e4++) {
                int h = e4 >> 1, e = e4 & 1;
                int col = wn * 64 + ni * 8 + q4 * 2 + e;
                float v = acc[mi][ni][e4] + __ldg(bias + n0 + col);
                rs[mi][h] += v; rss[mi][h] += v * v;
                acc[mi][ni][e4] = v;
            }
#pragma unroll
    for (int mi = 0; mi < MT; mi++)
#pragma unroll
        for (int h = 0; h < 2; h++) {
            float s = rs[mi][h], ss = rss[mi][h];
            s  += __shfl_xor_sync(0xffffffffu, s, 1);
            s  += __shfl_xor_sync(0xffffffffu, s, 2);
            ss += __shfl_xor_sync(0xffffffffu, ss, 1);
            ss += __shfl_xor_sync(0xffffffffu, ss, 2);
            if (q4 == 0) {
                int lr = wm * 32 + mi * 16 + gid + h * 8;
                sred[lr * 4 + wn] = s; ssred[lr * 4 + wn] = ss;
            }
        }
    __syncthreads();
#pragma unroll
    for (int mi = 0; mi < MT; mi++)
#pragma unroll
        for (int ni = 0; ni < 8; ni++) {
            int col = wn * 64 + ni * 8 + q4 * 2;
#pragma unroll
            for (int h = 0; h < 2; h++) {
                int lr = wm * 32 + mi * 16 + gid + h * 8;
                *(__nv_bfloat162*)(outH + (size_t)(m0 + lr) * 512 + n0 + col) =
                    __floats2bfloat162_rn(acc[mi][ni][h * 2 + 0], acc[mi][ni][h * 2 + 1]);
            }
        }
    if (tid < 64) {
        float s = 0.f, ss = 0.f;
#pragma unroll
        for (int j = 0; j < 4; j++) { s += sred[tid * 4 + j]; ss += ssred[tid * 4 + j]; }
        stats[(size_t)(m0 + tid) * 2 + blockIdx.y] = make_float2(s, ss);
    }
}

// ---------------- bf16 hf GEMM2 (R14-proven) ----------------
__global__ void __launch_bounds__(256, 2)
gemmh2_kernel(const __nv_bfloat16* __restrict__ A, const __nv_bfloat16* __restrict__ Bt,
              const float* __restrict__ bias, const float* __restrict__ p0,
              float* __restrict__ outv, float2* __restrict__ stats,
              const float* __restrict__ c1)
{
    constexpr int K = 512, KC = 64, SW = 72, SWB = SW * 2, NIT = K / KC, NN = 256;
    constexpr int MT = 2;

    extern __shared__ __align__(16) char dsmh[];
    __nv_bfloat16* As = (__nv_bfloat16*)dsmh;
    __nv_bfloat16* Bs = As + 2 * 64 * SW;
    float* sred = (float*)(Bs + 2 * NN * SW);
    float* ssred = sred + 256;
    float* spn = ssred + 256;

    int tid = threadIdx.x;
    int lane = tid & 31, warp = tid >> 5;
    int wn = warp & 3, wm = warp >> 2;
    int gid = lane >> 2, q4 = lane & 3;
    int m0 = blockIdx.x * 64;

    const __nv_bfloat16* Ab = A + (size_t)m0 * K;
    const __nv_bfloat16* BtB = Bt;

    if (warp == 0) {
        float s = 0.f;
        for (int i = lane; i < 256; i += 32) { float v = __ldg(p0 + i); s += v * v; }
#pragma unroll
        for (int o = 16; o; o >>= 1) s += __shfl_xor_sync(0xffffffffu, s, o);
        if (lane == 0) *spn = sqrtf(s);
    }

    uint32_t smem_a = (uint32_t)__cvta_generic_to_shared(As);
    uint32_t smem_b = (uint32_t)__cvta_generic_to_shared(Bs);

    auto cp_stage = [&](int st, int k0) {
#pragma unroll
        for (int j = 0; j < 2; j++) {
            int idx = tid + j * 256;
            int m = idx >> 3, kq = idx & 7;
            cp16(smem_a + (uint32_t)((st * 64 + m) * SW + kq * 8) * 2,
                 Ab + (size_t)m * K + k0 + kq * 8);
        }
#pragma unroll
        for (int j = 0; j < 8; j++) {
            int idx = tid + j * 256;
            int n = idx >> 3, kc = idx & 7;
            cp16(smem_b + (uint32_t)((st * NN + n) * SW + kc * 8) * 2,
                 BtB + (size_t)n * K + k0 + kc * 8);
        }
        cp_commit();
    };

    int ra = lane & 15;
    int ca = (lane >> 4) * 16;
    int rb = (lane & 7) + ((lane >> 4) << 3);
    int cb = (lane & 8) ? 16 : 0;

    float acc[MT][8][4];
#pragma unroll
    for (int mi = 0; mi < MT; mi++)
#pragma unroll
        for (int ni = 0; ni < 8; ni++)
#pragma unroll
            for (int e = 0; e < 4; e++) acc[mi][ni][e] = 0.f;

    cp_stage(0, 0);

    for (int it = 0; it < NIT; it++) {
        int cur = it & 1;
        bool more = (it + 1 < NIT);
        cp_wait<0>();
        __syncthreads();
        if (more) cp_stage(cur ^ 1, (it + 1) * KC);

        uint32_t abase = smem_a + (uint32_t)(cur * 64 * SW) * 2;
        uint32_t bbase = smem_b + (uint32_t)(cur * NN * SW) * 2;
#pragma unroll
        for (int kk = 0; kk < 4; kk++) {
            unsigned afr[MT][4];
#pragma unroll
            for (int mi = 0; mi < MT; mi++)
                ldsm4(afr[mi][0], afr[mi][1], afr[mi][2], afr[mi][3],
                      abase + (uint32_t)((wm * 32 + mi * 16 + ra) * SWB + ca + kk * 32));
            unsigned bfr[8][2];
#pragma unroll
            for (int nis = 0; nis < 8; nis += 2)
                ldsm4(bfr[nis][0], bfr[nis][1], bfr[nis + 1][0], bfr[nis + 1][1],
                      bbase + (uint32_t)((wn * 64 + nis * 8 + rb) * SWB + cb + kk * 32));
#pragma unroll
            for (int mi = 0; mi < MT; mi++)
#pragma unroll
                for (int ni = 0; ni < 8; ni++)
                    mma16(acc[mi][ni], afr[mi], bfr[ni]);
        }
    }

    float mu_rs[MT][2], rstd_v[MT][2];
#pragma unroll
    for (int mi = 0; mi < MT; mi++)
#pragma unroll
        for (int h = 0; h < 2; h++) {
            int lr = wm * 32 + mi * 16 + gid + h * 8;
            float2 s0 = stats[(size_t)(m0 + lr) * 2 + 0];
            float2 s1 = stats[(size_t)(m0 + lr) * 2 + 1];
            float sum = s0.x + s1.x, ss = s0.y + s1.y;
            float mu = sum * (1.f / 512.f);
            float var = ss * (1.f / 512.f) - mu * mu;
            float rstd = rsqrtf(var + 1e-5f);
            rstd_v[mi][h] = rstd;
            mu_rs[mi][h] = mu * rstd;
        }

    float rs[MT][2], rss[MT][2];
#pragma unroll
    for (int mi = 0; mi < MT; mi++) { rs[mi][0] = rs[mi][1] = 0.f; rss[mi][0] = rss[mi][1] = 0.f; }
#pragma unroll
    for (int mi = 0; mi < MT; mi++)
#pragma unroll
        for (int ni = 0; ni < 8; ni++)
#pragma unroll
            for (int e4 = 0; e4 < 4; e4++) {
                int h = e4 >> 1, e = e4 & 1;
                int col = wn * 64 + ni * 8 + q4 * 2 + e;
                float v = rstd_v[mi][h] * acc[mi][ni][e4] - mu_rs[mi][h] * __ldg(c1 + col)
                          + __ldg(bias + col);
                rs[mi][h] += v * __ldg(p0 + col);
                rss[mi][h] += v * v;
            }
#pragma unroll
    for (int mi = 0; mi < MT; mi++)
#pragma unroll
        for (int h = 0; h < 2; h++) {
            float s = rs[mi][h], ss = rss[mi][h];
            s  += __shfl_xor_sync(0xffffffffu, s, 1);
            s  += __shfl_xor_sync(0xffffffffu, s, 2);
            ss += __shfl_xor_sync(0xffffffffu, ss, 1);
            ss += __shfl_xor_sync(0xffffffffu, ss, 2);
            if (q4 == 0) {
                int lr = wm * 32 + mi * 16 + gid + h * 8;
                sred[lr * 4 + wn] = s; ssred[lr * 4 + wn] = ss;
            }
        }
    __syncthreads();
    if (tid < 64) {
        float dot = 0.f, nsq = 0.f;
#pragma unroll
        for (int j = 0; j < 4; j++) { dot += sred[tid * 4 + j]; nsq += ssred[tid * 4 + j]; }
        float nq = sqrtf(nsq);
        float sim = dot / (fmaxf(nq, 1e-8f) * fmaxf(*spn, 1e-8f));
        outv[m0 + tid] = fmaxf(sim, 0.f);
    }
}

// ---------------- K5: apply alpha/gate, inverse Haar, write output ----------------
__global__ void final_kernel(const float* __restrict__ xb, float* __restrict__ out)
{
    __shared__ __align__(16) float xs[8 * 128];
    int bi = blockIdx.x, c = blockIdx.y, b = blockIdx.z;
    size_t img = ((size_t)(b * C_ + c)) * H_;
    int t = threadIdx.x;
    int lrow = t >> 5, lcol = t & 31;
    ((float4*)xs)[t] = ((const float4*)(xb + (img + 8 * bi + lrow) * W_))[lcol];
    __syncthreads();
    int rp = t >> 6, j = t & 63;
    float2 top = ((const float2*)(xs + (2 * rp) * W_))[j];
    float2 bot = ((const float2*)(xs + (2 * rp + 1) * W_))[j];
    float p00 = top.x, p01 = top.y, p10 = bot.x, p11 = bot.y;
    float a  = 0.25f * (p00 + p01 + p10 + p11);
    float hb = 0.25f * (p00 - p01 + p10 - p11);
    float vb = 0.25f * (p00 + p01 - p10 - p11);
    float db = 0.25f * (p00 - p01 - p10 + p11);
    int hr = 4 * bi + rp, hc = j;
    int tok = (hr >> 1) * 32 + (hc >> 1);
    float ah = __ldg(&g_alpha[(0 * B_ + b) * TOK_HF + tok]);
    float av = __ldg(&g_alpha[(1 * B_ + b) * TOK_HF + tok]);
    float ad = __ldg(&g_alpha[(2 * B_ + b) * TOK_HF + tok]);
    int tg = (hr >> 2) * 16 + (hc >> 2);
    float gt = __ldg(&g_gate[((size_t)(b * 256 + tg)) * C_ + c]);
    float ae = a * gt, he = hb * ah, ve = vb * av, de = db * ad;
    float2 o0 = make_float2(ae + he + ve + de, ae - he + ve - de);
    float2 o1 = make_float2(ae + he - ve - de, ae - he - ve + de);
    int row0 = 8 * bi + 2 * rp;
    ((float2*)(out + (img + row0) * W_))[j] = o0;
    ((float2*)(out + (img + row0 + 1) * W_))[j] = o1;
}

static constexpr int SMEM_L = (2 * 64 * 68 + 2 * 128 * 68 + 512 + 4) * 4;        // ~104 KB
static constexpr int SMEM_Z = (2 * 64 * 64 + 2 * 256 * 72) * 2 + 512 * 4;        // ~92 KB
static constexpr int SMEM_H2 = (2 * 64 * 72 + 2 * 256 * 72) * 2 + (512 + 4) * 4; // ~92 KB

extern "C" void kernel_launch(void* const* d_in, const int* in_sizes, int n_in,
                              void* d_out, int out_size)
{
    const float* xb      = (const float*)d_in[0];
    const float* xsm     = (const float*)d_in[1];
    const float* hf_w1   = (const float*)d_in[2];
    const float* hf_b1   = (const float*)d_in[3];
    const float* hf_ln_w = (const float*)d_in[4];
    const float* hf_ln_b = (const float*)d_in[5];
    const float* hf_w2   = (const float*)d_in[6];
    const float* hf_b2   = (const float*)d_in[7];
    const float* hf_pr   = (const float*)d_in[8];
    const float* low_w   = (const float*)d_in[9];
    const float* low_b   = (const float*)d_in[10];
    const float* lf_w1   = (const float*)d_in[11];
    const float* lf_b1   = (const float*)d_in[12];
    const float* lf_ln_w = (const float*)d_in[13];
    const float* lf_ln_b = (const float*)d_in[14];
    const float* lf_w2   = (const float*)d_in[15];
    const float* lf_b2   = (const float*)d_in[16];

    void *pz, *pps, *pHh, *pHlf, *pktok, *pgate, *palpha, *pwt, *pwth, *psh, *psl, *pc1, *pbp;
    cudaGetSymbolAddress(&pz, g_z);
    cudaGetSymbolAddress(&pps, g_ps);
    cudaGetSymbolAddress(&pHh, g_Hh);
    cudaGetSymbolAddress(&pHlf, g_Hlf);
    cudaGetSymbolAddress(&pktok, g_ktok);
    cudaGetSymbolAddress(&pgate, g_gate);
    cudaGetSymbolAddress(&palpha, g_alpha);
    cudaGetSymbolAddress(&pwt, g_wt);
    cudaGetSymbolAddress(&pwth, g_wth);
    cudaGetSymbolAddress(&psh, g_stats_hf);
    cudaGetSymbolAddress(&psl, g_stats_lf);
    cudaGetSymbolAddress(&pc1, g_c1);
    cudaGetSymbolAddress(&pbp, g_bp);
    const float* wt = (const float*)pwt;
    const __nv_bfloat16* wth = (const __nv_bfloat16*)pwth;
    float2* sh = (float2*)psh;
    float2* sl = (float2*)psl;
    const float* c1 = (const float*)pc1;
    const float* bp = (const float*)pbp;

    cudaFuncSetAttribute((const void*)gemmz_kernel,
                         cudaFuncAttributeMaxDynamicSharedMemorySize, SMEM_Z);
    cudaFuncSetAttribute((const void*)gemmh2_kernel,
                         cudaFuncAttributeMaxDynamicSharedMemorySize, SMEM_H2);
    cudaFuncSetAttribute((const void*)gemm256_kernel<512, 1, 0, 256, 128, 64, 2>,
                         cudaFuncAttributeMaxDynamicSharedMemorySize, SMEM_L);
    cudaFuncSetAttribute((const void*)gemm256_kernel<256, 2, 1, 512, 128, 64, 4>,
                         cudaFuncAttributeMaxDynamicSharedMemorySize, SMEM_L);
    cudaFuncSetAttribute((const void*)gemm256_kernel<512, 2, 3, 256, 128, 64, 4>,
                         cudaFuncAttributeMaxDynamicSharedMemorySize, SMEM_L);

    // Order: gemmz is the 4th launch (ncu profiles it).
    transpose5_kernel<<<dim3(16, 16, 5), dim3(32, 8)>>>(hf_w1, hf_w2, low_w, lf_w1, lf_w2,
                                                        hf_ln_w, lf_ln_w);
    haar_z_kernel<<<dim3(4, 256, 16), 256>>>(xb);
    fold_kernel<<<2, 256>>>(hf_w2, hf_ln_b, hf_b2, lf_w2, lf_ln_b, lf_b2);

    // hf chain
    gemmz_kernel<<<dim3(M_HF / 64, 2), 256, SMEM_Z>>>(
        (const __nv_bfloat16*)pz, wth, hf_b1, (__nv_bfloat16*)pHh, sh);
    pool_small_kernel<<<dim3(512, 16), 256>>>(xsm);
    gemmh2_kernel<<<M_HF / 64, 256, SMEM_H2>>>(
        (const __nv_bfloat16*)pHh, wth + 512 * 256, bp + 0, hf_pr, (float*)palpha, sh, c1 + 0);

    // lf chain (tf32, NN=128, KC=64 — more CTAs, half the stalls)
    gemm256_kernel<512, 1, 0, 256, 128, 64, 2><<<dim3(M_LF / 64, 2), 256, SMEM_L>>>(
        (const float*)pps, wt + 2 * 512 * 256, low_b, (float*)pktok, nullptr, nullptr);
    gemm256_kernel<256, 2, 1, 512, 128, 64, 4><<<dim3(M_LF / 64, 4), 256, SMEM_L>>>(
        (const float*)pktok, wt + 3 * 512 * 256, lf_b1, (float*)pHlf, sl, nullptr);
    gemm256_kernel<512, 2, 3, 256, 128, 64, 4><<<dim3(M_LF / 64, 2), 256, SMEM_L>>>(
        (const float*)pHlf, wt + 4 * 512 * 256, bp + 256, (float*)pgate, sl, c1 + 256);

    final_kernel<<<dim3(16, 256, 16), 256>>>(xb, (float*)d_out);
}

// round 16
// speedup vs baseline: 1.1929x; 1.0814x over previous
#include <cuda_runtime.h>
#include <cuda_bf16.h>
#include <cstdint>
#include <math.h>

#define DEV_INLINE __device__ __forceinline__

static constexpr int B_ = 16, C_ = 256, H_ = 128, W_ = 128;
static constexpr int CS = 512;
static constexpr int TOK_HF = 1024;
static constexpr int M_HF = 3 * B_ * TOK_HF;     // 49152
static constexpr int M_LF = B_ * 256;            // 4096

// ---------------- scratch ----------------
__device__ __nv_bfloat16 g_z[3ULL * B_ * C_ * TOK_HF];   // [band][b][c][tok] bf16
__device__ float g_ps[(size_t)B_ * CS * 256];            // [b][s][tok]
__device__ __nv_bfloat16 g_Hh[(size_t)M_HF * 512];       // RAW hidden (hf) bf16
__device__ float g_Hlf[(size_t)M_LF * 512];              // RAW hidden (lf) fp32
__device__ float g_ktok[(size_t)M_LF * C_];
__device__ float g_gate[(size_t)M_LF * C_];
__device__ float g_alpha[3 * B_ * TOK_HF];
__device__ float g_wt[5ULL * 512 * 256];                 // transposed weights [n][k] fp32
__device__ __nv_bfloat16 g_wth[2ULL * 512 * 256];        // bf16: [0]=hf_w1t, [1]=hf_w2t'
__device__ float2 g_stats_hf[(size_t)M_HF * 2];
__device__ float2 g_stats_lf[(size_t)M_LF * 4];
__device__ float g_c1[2 * 256];
__device__ float g_bp[2 * 256];

// ---------------- weight transpose (+ LN-weight folding + bf16 copies) ----------------
__global__ void transpose5_kernel(const float* __restrict__ w0, const float* __restrict__ w1,
                                  const float* __restrict__ w2, const float* __restrict__ w3,
                                  const float* __restrict__ w4,
                                  const float* __restrict__ hf_lnw, const float* __restrict__ lf_lnw)
{
    __shared__ float tile[32][33];
    int mi = blockIdx.z;
    const float* in; int R, Cc; const float* lnw = nullptr;
    switch (mi) {
        case 0: in = w0; R = 256; Cc = 512; break;
        case 1: in = w1; R = 512; Cc = 256; lnw = hf_lnw; break;
        case 2: in = w2; R = 512; Cc = 256; break;
        case 3: in = w3; R = 256; Cc = 512; break;
        default: in = w4; R = 512; Cc = 256; lnw = lf_lnw; break;
    }
    float* out = g_wt + (size_t)mi * 512 * 256;
    int bx = blockIdx.x * 32, by = blockIdx.y * 32;
    if (bx >= Cc || by >= R) return;
    int tx = threadIdx.x, ty = threadIdx.y;
#pragma unroll
    for (int j = 0; j < 32; j += 8) {
        int row = by + ty + j;
        float v = in[(size_t)row * Cc + bx + tx];
        if (lnw) v *= __ldg(lnw + row);
        tile[ty + j][tx] = v;
    }
    __syncthreads();
#pragma unroll
    for (int j = 0; j < 32; j += 8) {
        float v = tile[tx][ty + j];
        size_t oidx = (size_t)(bx + ty + j) * R + by + tx;
        out[oidx] = v;
        if (mi == 0) g_wth[oidx] = __float2bfloat16(v);
        if (mi == 1) g_wth[512 * 256 + oidx] = __float2bfloat16(v);
    }
}

__global__ void fold_kernel(const float* __restrict__ w2a, const float* __restrict__ lnba,
                            const float* __restrict__ b2a,
                            const float* __restrict__ w2b, const float* __restrict__ lnbb,
                            const float* __restrict__ b2b)
{
    int mi = blockIdx.x;
    int n = threadIdx.x;
    const float* wt = g_wt + (size_t)(mi ? 4 : 1) * 512 * 256;
    const float* w2 = mi ? w2b : w2a;
    const float* lnb = mi ? lnbb : lnba;
    const float* b2 = mi ? b2b : b2a;
    float s1 = 0.f, s2 = 0.f;
    for (int k = 0; k < 512; k++) {
        s1 += wt[(size_t)n * 512 + k];
        s2 += lnb[k] * w2[(size_t)k * 256 + n];
    }
    g_c1[mi * 256 + n] = s1;
    g_bp[mi * 256 + n] = b2[n] + s2;
}

// ---------------- K1: Haar bands -> abs-pooled z tokens (bf16 out) ----------------
__global__ void haar_z_kernel(const float* __restrict__ xb)
{
    int tid = threadIdx.x;
    int tk = blockIdx.x * 256 + tid;
    int c = blockIdx.y, b = blockIdx.z;
    int ti = tk >> 5, tj = tk & 31;
    const float* base = xb + ((size_t)(b * C_ + c) * H_ + 4 * ti) * W_ + 4 * tj;
    float4 r0 = *(const float4*)(base);
    float4 r1 = *(const float4*)(base + W_);
    float4 r2 = *(const float4*)(base + 2 * W_);
    float4 r3 = *(const float4*)(base + 3 * W_);
    float zh = 0.f, zv = 0.f, zd = 0.f;
#define HBLK(p00, p01, p10, p11) \
    zh += fabsf((p00) - (p01) + (p10) - (p11)); \
    zv += fabsf((p00) + (p01) - (p10) - (p11)); \
    zd += fabsf((p00) - (p01) - (p10) + (p11));
    HBLK(r0.x, r0.y, r1.x, r1.y)
    HBLK(r0.z, r0.w, r1.z, r1.w)
    HBLK(r2.x, r2.y, r3.x, r3.y)
    HBLK(r2.z, r2.w, r3.z, r3.w)
#undef HBLK
    const float s = 0.0625f;
    size_t base_o = ((size_t)(b) * C_ + c) * TOK_HF + tk;
    const size_t BS = (size_t)B_ * C_ * TOK_HF;
    g_z[base_o]          = __float2bfloat16(zh * s);
    g_z[BS + base_o]     = __float2bfloat16(zv * s);
    g_z[2 * BS + base_o] = __float2bfloat16(zd * s);
}

// ---------------- K2: 4x4 mean-pool of x_small ----------------
__global__ void pool_small_kernel(const float* __restrict__ xsm)
{
    int s = blockIdx.x, b = blockIdx.y;
    const float* src = xsm + ((size_t)(b * CS + s)) * 64 * 64;
    int t = threadIdx.x;
    int tj = t & 15, ti = t >> 4;
    float sum = 0.f;
#pragma unroll
    for (int r = 0; r < 4; r++) {
        float4 v = *(const float4*)(src + (4 * ti + r) * 64 + 4 * tj);
        sum += v.x + v.y + v.z + v.w;
    }
    g_ps[((size_t)(b * CS + s)) * 256 + t] = sum * (1.f / 16.f);
}

// ---------------- asm helpers ----------------
DEV_INLINE void mma8(float* c, const unsigned* a, const unsigned* b) {
    asm volatile("mma.sync.aligned.m16n8k8.row.col.f32.tf32.tf32.f32 "
                 "{%0,%1,%2,%3}, {%4,%5,%6,%7}, {%8,%9}, {%0,%1,%2,%3};"
                 : "+f"(c[0]), "+f"(c[1]), "+f"(c[2]), "+f"(c[3])
                 : "r"(a[0]), "r"(a[1]), "r"(a[2]), "r"(a[3]),
                   "r"(b[0]), "r"(b[1]));
}
DEV_INLINE void mma16(float* c, const unsigned* a, const unsigned* b) {
    asm volatile("mma.sync.aligned.m16n8k16.row.col.f32.bf16.bf16.f32 "
                 "{%0,%1,%2,%3}, {%4,%5,%6,%7}, {%8,%9}, {%0,%1,%2,%3};"
                 : "+f"(c[0]), "+f"(c[1]), "+f"(c[2]), "+f"(c[3])
                 : "r"(a[0]), "r"(a[1]), "r"(a[2]), "r"(a[3]),
                   "r"(b[0]), "r"(b[1]));
}
DEV_INLINE void ldsm4(unsigned& r0, unsigned& r1, unsigned& r2, unsigned& r3, uint32_t addr) {
    asm volatile("ldmatrix.sync.aligned.m8n8.x4.shared.b16 {%0,%1,%2,%3}, [%4];"
                 : "=r"(r0), "=r"(r1), "=r"(r2), "=r"(r3) : "r"(addr));
}
DEV_INLINE void ldsm4t(unsigned& r0, unsigned& r1, unsigned& r2, unsigned& r3, uint32_t addr) {
    asm volatile("ldmatrix.sync.aligned.m8n8.x4.trans.shared.b16 {%0,%1,%2,%3}, [%4];"
                 : "=r"(r0), "=r"(r1), "=r"(r2), "=r"(r3) : "r"(addr));
}
DEV_INLINE void cp16(uint32_t s, const void* g) {
    asm volatile("cp.async.cg.shared.global [%0], [%1], 16;" :: "r"(s), "l"(g));
}
DEV_INLINE void cp_commit() { asm volatile("cp.async.commit_group;"); }
template<int NN> DEV_INLINE void cp_wait() { asm volatile("cp.async.wait_group %0;" :: "n"(NN)); }

// ---------------- tf32 64xNN-tile GEMM, generic NN/KC (lf chain) ----------------
template<int K, int AMODE, int EPI, int OSTRIDE, int NN, int KC, int NST>
__global__ void __launch_bounds__(256, 2)
gemm256_kernel(const float* __restrict__ A, const float* __restrict__ Bt,
               const float* __restrict__ bias, float* __restrict__ out,
               float2* __restrict__ stats, const float* __restrict__ c1)
{
    constexpr int SW = KC + 4, SWB = SW * 4, NIT = K / KC;
    constexpr int MT = 2, NT = NN / 32;
    constexpr int CPR = KC / 4;

    extern __shared__ __align__(16) float dsm[];
    float* As = dsm;
    float* Bs = As + 2 * 64 * SW;
    float* sred = Bs + 2 * NN * SW;
    float* ssred = sred + 256;

    int tid = threadIdx.x;
    int lane = tid & 31, warp = tid >> 5;
    int wn = warp & 3, wm = warp >> 2;
    int gid = lane >> 2, q4 = lane & 3;
    int m0 = blockIdx.x * 64;
    int n0 = blockIdx.y * NN;

    const float* Ab; int astride = 0;
    if (AMODE == 1) { Ab = A + (size_t)(m0 >> 8) * (CS * 256) + (m0 & 255); astride = 256; }
    else { Ab = A + (size_t)m0 * K; }
    const float* BtB = Bt + (size_t)n0 * K;

    uint32_t smem_a = (uint32_t)__cvta_generic_to_shared(As);
    uint32_t smem_b = (uint32_t)__cvta_generic_to_shared(Bs);

    int la_m = tid & 63, la_kg = tid >> 6;
    float areg[CPR];
    auto load_A = [&](int k0) {
        if (AMODE == 1) {
#pragma unroll
            for (int i = 0; i < CPR; i++)
                areg[i] = __ldg(Ab + (size_t)(k0 + la_kg * CPR + i) * astride + la_m);
        }
    };
    auto sts_A = [&](int st) {
        if (AMODE == 1) {
            float* p = As + st * 64 * SW + la_m * SW + la_kg * CPR;
#pragma unroll
            for (int i = 0; i < CPR; i += 4)
                *(float4*)(p + i) = make_float4(areg[i], areg[i + 1], areg[i + 2], areg[i + 3]);
        }
    };
    auto cp_stage = [&](int st, int k0) {
        if (AMODE == 2) {
#pragma unroll
            for (int j = 0; j < 64 * CPR / 256; j++) {
                int idx = tid + j * 256;
                int m = idx / CPR, kq = idx % CPR;
                cp16(smem_a + (uint32_t)((st * 64 + m) * SW + kq * 4) * 4,
                     Ab + (size_t)m * K + k0 + kq * 4);
            }
        }
#pragma unroll
        for (int j = 0; j < NN * CPR / 256; j++) {
            int idx = tid + j * 256;
            int n = idx / CPR, kc = idx % CPR;
            cp16(smem_b + (uint32_t)((st * NN + n) * SW + kc * 4) * 4,
                 BtB + (size_t)n * K + k0 + kc * 4);
        }
        cp_commit();
    };

    int ra = lane & 15;
    int ca = (lane & 16) ? 16 : 0;
    int rb = (lane & 7) + ((lane >> 4) << 3);
    int cb = (lane & 8) ? 16 : 0;

    float acc[MT][NT][4];
#pragma unroll
    for (int mi = 0; mi < MT; mi++)
#pragma unroll
        for (int ni = 0; ni < NT; ni++)
#pragma unroll
            for (int e = 0; e < 4; e++) acc[mi][ni][e] = 0.f;

    load_A(0);
    cp_stage(0, 0);
    sts_A(0);
    if (NIT > 1) load_A(KC);

    for (int it = 0; it < NIT; it++) {
        int cur = it & 1;
        bool more = (it + 1 < NIT);
        cp_wait<0>();
        __syncthreads();
        if (more) {
            cp_stage(cur ^ 1, (it + 1) * KC);
            sts_A(cur ^ 1);
        }
        if (it + 2 < NIT) load_A((it + 2) * KC);

        uint32_t abase = smem_a + (uint32_t)(cur * 64 * SW) * 4;
        uint32_t bbase = smem_b + (uint32_t)(cur * NN * SW) * 4;
#pragma unroll
        for (int kk = 0; kk < KC; kk += 8) {
            unsigned afr[MT][4];
#pragma unroll
            for (int mi = 0; mi < MT; mi++)
                ldsm4(afr[mi][0], afr[mi][1], afr[mi][2], afr[mi][3],
                      abase + (uint32_t)((wm * 32 + mi * 16 + ra) * SWB + kk * 4 + ca));
            unsigned bfr[NT][2];
#pragma unroll
            for (int nis = 0; nis < NT; nis += 2)
                ldsm4(bfr[nis][0], bfr[nis][1], bfr[nis + 1][0], bfr[nis + 1][1],
                      bbase + (uint32_t)((wn * (NN / 4) + nis * 8 + rb) * SWB + kk * 4 + cb));
#pragma unroll
            for (int mi = 0; mi < MT; mi++)
#pragma unroll
                for (int ni = 0; ni < NT; ni++)
                    mma8(acc[mi][ni], afr[mi], bfr[ni]);
        }
    }

    float mu_rs[MT][2], rstd_v[MT][2];
    if (EPI == 3) {
#pragma unroll
        for (int mi = 0; mi < MT; mi++)
#pragma unroll
            for (int h = 0; h < 2; h++) {
                int lr = wm * 32 + mi * 16 + gid + h * 8;
                float sum = 0.f, ss = 0.f;
#pragma unroll
                for (int j = 0; j < NST; j++) {
                    float2 s = stats[(size_t)(m0 + lr) * NST + j];
                    sum += s.x; ss += s.y;
                }
                float mu = sum * (1.f / 512.f);
                float var = ss * (1.f / 512.f) - mu * mu;
                float rstd = rsqrtf(var + 1e-5f);
                rstd_v[mi][h] = rstd;
                mu_rs[mi][h] = mu * rstd;
            }
    }

    float rs[MT][2], rss[MT][2];
#pragma unroll
    for (int mi = 0; mi < MT; mi++) { rs[mi][0] = rs[mi][1] = 0.f; rss[mi][0] = rss[mi][1] = 0.f; }

#pragma unroll
    for (int mi = 0; mi < MT; mi++)
#pragma unroll
        for (int ni = 0; ni < NT; ni++)
#pragma unroll
            for (int e4 = 0; e4 < 4; e4++) {
                int h = e4 >> 1, e = e4 & 1;
                int col = wn * (NN / 4) + ni * 8 + q4 * 2 + e;
                float v;
                if (EPI <= 1) {
                    v = acc[mi][ni][e4] + __ldg(bias + n0 + col);
                    if (EPI == 1) { rs[mi][h] += v; rss[mi][h] += v * v; }
                } else {
                    v = rstd_v[mi][h] * acc[mi][ni][e4] - mu_rs[mi][h] * __ldg(c1 + n0 + col)
                        + __ldg(bias + n0 + col);
                }
                acc[mi][ni][e4] = v;
            }

    if (EPI == 1) {
#pragma unroll
        for (int mi = 0; mi < MT; mi++)
#pragma unroll
            for (int h = 0; h < 2; h++) {
                float s = rs[mi][h], ss = rss[mi][h];
                s  += __shfl_xor_sync(0xffffffffu, s, 1);
                s  += __shfl_xor_sync(0xffffffffu, s, 2);
                ss += __shfl_xor_sync(0xffffffffu, ss, 1);
                ss += __shfl_xor_sync(0xffffffffu, ss, 2);
                if (q4 == 0) {
                    int lr = wm * 32 + mi * 16 + gid + h * 8;
                    sred[lr * 4 + wn] = s; ssred[lr * 4 + wn] = ss;
                }
            }
        __syncthreads();
    }

#pragma unroll
    for (int mi = 0; mi < MT; mi++)
#pragma unroll
        for (int ni = 0; ni < NT; ni++) {
            int col = wn * (NN / 4) + ni * 8 + q4 * 2;
#pragma unroll
            for (int h = 0; h < 2; h++) {
                int lr = wm * 32 + mi * 16 + gid + h * 8;
                float vx = acc[mi][ni][h * 2 + 0], vy = acc[mi][ni][h * 2 + 1];
                if (EPI == 3) { vx = 1.f / (1.f + expf(-vx)); vy = 1.f / (1.f + expf(-vy)); }
                *(float2*)(out + (size_t)(m0 + lr) * OSTRIDE + n0 + col) = make_float2(vx, vy);
            }
        }
    if (EPI == 1) {
        if (tid < 64) {
            float s = 0.f, ss = 0.f;
#pragma unroll
            for (int j = 0; j < 4; j++) { s += sred[tid * 4 + j]; ss += ssred[tid * 4 + j]; }
            stats[(size_t)(m0 + tid) * NST + blockIdx.y] = make_float2(s, ss);
        }
    }
}

// ---------------- bf16 GEMM1-hf with cp.async A + ldmatrix.trans (R14-proven) ----------------
__global__ void __launch_bounds__(256, 2)
gemmz_kernel(const __nv_bfloat16* __restrict__ Z, const __nv_bfloat16* __restrict__ Bt,
             const float* __restrict__ bias, __nv_bfloat16* __restrict__ outH,
             float2* __restrict__ stats)
{
    constexpr int KC = 64, NIT = 256 / KC;
    constexpr int SWBH = 72;
    constexpr int MT = 2;

    extern __shared__ __align__(16) char dsmz[];
    __nv_bfloat16* As = (__nv_bfloat16*)dsmz;
    __nv_bfloat16* Bs = As + 2 * 64 * 64;
    float* sred = (float*)(Bs + 2 * 256 * SWBH);
    float* ssred = sred + 256;

    int tid = threadIdx.x;
    int lane = tid & 31, warp = tid >> 5;
    int wn = warp & 3, wm = warp >> 2;
    int gid = lane >> 2, q4 = lane & 3;
    int m0 = blockIdx.x * 64;
    int n0 = blockIdx.y * 256;

    const __nv_bfloat16* Ab = Z + (size_t)(m0 >> 10) * (C_ * TOK_HF) + (m0 & 1023);
    const __nv_bfloat16* BtB = Bt + (size_t)n0 * 256;

    uint32_t smem_a = (uint32_t)__cvta_generic_to_shared(As);
    uint32_t smem_b = (uint32_t)__cvta_generic_to_shared(Bs);

    auto cp_stage = [&](int st, int k0) {
#pragma unroll
        for (int j = 0; j < 2; j++) {
            int idx = tid + j * 256;
            int k = idx >> 3, mc = idx & 7;
            cp16(smem_a + (uint32_t)((st * 64 + k) * 128 + ((mc * 16) ^ ((k & 7) << 4))),
                 Ab + (size_t)(k0 + k) * TOK_HF + mc * 8);
        }
#pragma unroll
        for (int j = 0; j < 8; j++) {
            int idx = tid + j * 256;
            int n = idx >> 3, kc = idx & 7;
            cp16(smem_b + (uint32_t)((st * 256 + n) * SWBH + kc * 8) * 2,
                 BtB + (size_t)n * 256 + k0 + kc * 8);
        }
        cp_commit();
    };

    int ksrc = (lane & 7) + ((lane >> 4) << 3);
    int moff = ((lane >> 3) & 1) << 3;
    int rb = (lane & 7) + ((lane >> 4) << 3);
    int cb = (lane & 8) ? 16 : 0;

    float acc[MT][8][4];
#pragma unroll
    for (int mi = 0; mi < MT; mi++)
#pragma unroll
        for (int ni = 0; ni < 8; ni++)
#pragma unroll
            for (int e = 0; e < 4; e++) acc[mi][ni][e] = 0.f;

    cp_stage(0, 0);

    for (int it = 0; it < NIT; it++) {
        int cur = it & 1;
        bool more = (it + 1 < NIT);
        cp_wait<0>();
        __syncthreads();
        if (more) cp_stage(cur ^ 1, (it + 1) * KC);

        uint32_t abase = smem_a + (uint32_t)(cur * 64 * 128);
        uint32_t bbase = smem_b + (uint32_t)(cur * 256 * SWBH) * 2;
#pragma unroll
        for (int kk = 0; kk < 4; kk++) {
            int krow = kk * 16 + ksrc;
            unsigned afr[MT][4];
#pragma unroll
            for (int mi = 0; mi < MT; mi++) {
                int mb = (wm * 32 + mi * 16 + moff) * 2;
                ldsm4t(afr[mi][0], afr[mi][1], afr[mi][2], afr[mi][3],
                       abase + (uint32_t)(krow * 128 + (mb ^ ((ksrc & 7) << 4))));
            }
            unsigned bfr[8][2];
#pragma unroll
            for (int nis = 0; nis < 8; nis += 2)
                ldsm4(bfr[nis][0], bfr[nis][1], bfr[nis + 1][0], bfr[nis + 1][1],
                      bbase + (uint32_t)((wn * 64 + nis * 8 + rb) * (SWBH * 2) + cb + kk * 32));
#pragma unroll
            for (int mi = 0; mi < MT; mi++)
#pragma unroll
                for (int ni = 0; ni < 8; ni++)
                    mma16(acc[mi][ni], afr[mi], bfr[ni]);
        }
    }

    float rs[MT][2], rss[MT][2];
#pragma unroll
    for (int mi = 0; mi < MT; mi++) { rs[mi][0] = rs[mi][1] = 0.f; rss[mi][0] = rss[mi][1] = 0.f; }
#pragma unroll
    for (int mi = 0; mi < MT; mi++)
#pragma unroll
        for (int ni = 0; ni < 8; ni++)
#pragma unroll
            for (int e4 = 0; e4 < 4; e4++) {
                int h = e4 >> 1, e = e4 & 1;
                int col = wn * 64 + ni * 8 + q4 * 2 + e;
                float v = acc[mi][ni][e4] + __ldg(bias + n0 + col);
                rs[mi][h] += v; rss[mi][h] += v * v;
                acc[mi][ni][e4] = v;
            }
#pragma unroll
    for (int mi = 0; mi < MT; mi++)
#pragma unroll
        for (int h = 0; h < 2; h++) {
            float s = rs[mi][h], ss = rss[mi][h];
            s  += __shfl_xor_sync(0xffffffffu, s, 1);
            s  += __shfl_xor_sync(0xffffffffu, s, 2);
            ss += __shfl_xor_sync(0xffffffffu, ss, 1);
            ss += __shfl_xor_sync(0xffffffffu, ss, 2);
            if (q4 == 0) {
                int lr = wm * 32 + mi * 16 + gid + h * 8;
                sred[lr * 4 + wn] = s; ssred[lr * 4 + wn] = ss;
            }
        }
    __syncthreads();
#pragma unroll
    for (int mi = 0; mi < MT; mi++)
#pragma unroll
        for (int ni = 0; ni < 8; ni++) {
            int col = wn * 64 + ni * 8 + q4 * 2;
#pragma unroll
            for (int h = 0; h < 2; h++) {
                int lr = wm * 32 + mi * 16 + gid + h * 8;
                *(__nv_bfloat162*)(outH + (size_t)(m0 + lr) * 512 + n0 + col) =
                    __floats2bfloat162_rn(acc[mi][ni][h * 2 + 0], acc[mi][ni][h * 2 + 1]);
            }
        }
    if (tid < 64) {
        float s = 0.f, ss = 0.f;
#pragma unroll
        for (int j = 0; j < 4; j++) { s += sred[tid * 4 + j]; ss += ssred[tid * 4 + j]; }
        stats[(size_t)(m0 + tid) * 2 + blockIdx.y] = make_float2(s, ss);
    }
}

// ---------------- bf16 hf GEMM2 (R14-proven) ----------------
__global__ void __launch_bounds__(256, 2)
gemmh2_kernel(const __nv_bfloat16* __restrict__ A, const __nv_bfloat16* __restrict__ Bt,
              const float* __restrict__ bias, const float* __restrict__ p0,
              float* __restrict__ outv, float2* __restrict__ stats,
              const float* __restrict__ c1)
{
    constexpr int K = 512, KC = 64, SW = 72, SWB = SW * 2, NIT = K / KC, NN = 256;
    constexpr int MT = 2;

    extern __shared__ __align__(16) char dsmh[];
    __nv_bfloat16* As = (__nv_bfloat16*)dsmh;
    __nv_bfloat16* Bs = As + 2 * 64 * SW;
    float* sred = (float*)(Bs + 2 * NN * SW);
    float* ssred = sred + 256;
    float* spn = ssred + 256;

    int tid = threadIdx.x;
    int lane = tid & 31, warp = tid >> 5;
    int wn = warp & 3, wm = warp >> 2;
    int gid = lane >> 2, q4 = lane & 3;
    int m0 = blockIdx.x * 64;

    const __nv_bfloat16* Ab = A + (size_t)m0 * K;
    const __nv_bfloat16* BtB = Bt;

    if (warp == 0) {
        float s = 0.f;
        for (int i = lane; i < 256; i += 32) { float v = __ldg(p0 + i); s += v * v; }
#pragma unroll
        for (int o = 16; o; o >>= 1) s += __shfl_xor_sync(0xffffffffu, s, o);
        if (lane == 0) *spn = sqrtf(s);
    }

    uint32_t smem_a = (uint32_t)__cvta_generic_to_shared(As);
    uint32_t smem_b = (uint32_t)__cvta_generic_to_shared(Bs);

    auto cp_stage = [&](int st, int k0) {
#pragma unroll
        for (int j = 0; j < 2; j++) {
            int idx = tid + j * 256;
            int m = idx >> 3, kq = idx & 7;
            cp16(smem_a + (uint32_t)((st * 64 + m) * SW + kq * 8) * 2,
                 Ab + (size_t)m * K + k0 + kq * 8);
        }
#pragma unroll
        for (int j = 0; j < 8; j++) {
            int idx = tid + j * 256;
            int n = idx >> 3, kc = idx & 7;
            cp16(smem_b + (uint32_t)((st * NN + n) * SW + kc * 8) * 2,
                 BtB + (size_t)n * K + k0 + kc * 8);
        }
        cp_commit();
    };

    int ra = lane & 15;
    int ca = (lane >> 4) * 16;
    int rb = (lane & 7) + ((lane >> 4) << 3);
    int cb = (lane & 8) ? 16 : 0;

    float acc[MT][8][4];
#pragma unroll
    for (int mi = 0; mi < MT; mi++)
#pragma unroll
        for (int ni = 0; ni < 8; ni++)
#pragma unroll
            for (int e = 0; e < 4; e++) acc[mi][ni][e] = 0.f;

    cp_stage(0, 0);

    for (int it = 0; it < NIT; it++) {
        int cur = it & 1;
        bool more = (it + 1 < NIT);
        cp_wait<0>();
        __syncthreads();
        if (more) cp_stage(cur ^ 1, (it + 1) * KC);

        uint32_t abase = smem_a + (uint32_t)(cur * 64 * SW) * 2;
        uint32_t bbase = smem_b + (uint32_t)(cur * NN * SW) * 2;
#pragma unroll
        for (int kk = 0; kk < 4; kk++) {
            unsigned afr[MT][4];
#pragma unroll
            for (int mi = 0; mi < MT; mi++)
                ldsm4(afr[mi][0], afr[mi][1], afr[mi][2], afr[mi][3],
                      abase + (uint32_t)((wm * 32 + mi * 16 + ra) * SWB + ca + kk * 32));
            unsigned bfr[8][2];
#pragma unroll
            for (int nis = 0; nis < 8; nis += 2)
                ldsm4(bfr[nis][0], bfr[nis][1], bfr[nis + 1][0], bfr[nis + 1][1],
                      bbase + (uint32_t)((wn * 64 + nis * 8 + rb) * SWB + cb + kk * 32));
#pragma unroll
            for (int mi = 0; mi < MT; mi++)
#pragma unroll
                for (int ni = 0; ni < 8; ni++)
                    mma16(acc[mi][ni], afr[mi], bfr[ni]);
        }
    }

    float mu_rs[MT][2], rstd_v[MT][2];
#pragma unroll
    for (int mi = 0; mi < MT; mi++)
#pragma unroll
        for (int h = 0; h < 2; h++) {
            int lr = wm * 32 + mi * 16 + gid + h * 8;
            float2 s0 = stats[(size_t)(m0 + lr) * 2 + 0];
            float2 s1 = stats[(size_t)(m0 + lr) * 2 + 1];
            float sum = s0.x + s1.x, ss = s0.y + s1.y;
            float mu = sum * (1.f / 512.f);
            float var = ss * (1.f / 512.f) - mu * mu;
            float rstd = rsqrtf(var + 1e-5f);
            rstd_v[mi][h] = rstd;
            mu_rs[mi][h] = mu * rstd;
        }

    float rs[MT][2], rss[MT][2];
#pragma unroll
    for (int mi = 0; mi < MT; mi++) { rs[mi][0] = rs[mi][1] = 0.f; rss[mi][0] = rss[mi][1] = 0.f; }
#pragma unroll
    for (int mi = 0; mi < MT; mi++)
#pragma unroll
        for (int ni = 0; ni < 8; ni++)
#pragma unroll
            for (int e4 = 0; e4 < 4; e4++) {
                int h = e4 >> 1, e = e4 & 1;
                int col = wn * 64 + ni * 8 + q4 * 2 + e;
                float v = rstd_v[mi][h] * acc[mi][ni][e4] - mu_rs[mi][h] * __ldg(c1 + col)
                          + __ldg(bias + col);
                rs[mi][h] += v * __ldg(p0 + col);
                rss[mi][h] += v * v;
            }
#pragma unroll
    for (int mi = 0; mi < MT; mi++)
#pragma unroll
        for (int h = 0; h < 2; h++) {
            float s = rs[mi][h], ss = rss[mi][h];
            s  += __shfl_xor_sync(0xffffffffu, s, 1);
            s  += __shfl_xor_sync(0xffffffffu, s, 2);
            ss += __shfl_xor_sync(0xffffffffu, ss, 1);
            ss += __shfl_xor_sync(0xffffffffu, ss, 2);
            if (q4 == 0) {
                int lr = wm * 32 + mi * 16 + gid + h * 8;
                sred[lr * 4 + wn] = s; ssred[lr * 4 + wn] = ss;
            }
        }
    __syncthreads();
    if (tid < 64) {
        float dot = 0.f, nsq = 0.f;
#pragma unroll
        for (int j = 0; j < 4; j++) { dot += sred[tid * 4 + j]; nsq += ssred[tid * 4 + j]; }
        float nq = sqrtf(nsq);
        float sim = dot / (fmaxf(nq, 1e-8f) * fmaxf(*spn, 1e-8f));
        outv[m0 + tid] = fmaxf(sim, 0.f);
    }
}

// ---------------- K5: apply alpha/gate, inverse Haar, write output ----------------
__global__ void final_kernel(const float* __restrict__ xb, float* __restrict__ out)
{
    __shared__ __align__(16) float xs[8 * 128];
    int bi = blockIdx.x, c = blockIdx.y, b = blockIdx.z;
    size_t img = ((size_t)(b * C_ + c)) * H_;
    int t = threadIdx.x;
    int lrow = t >> 5, lcol = t & 31;
    ((float4*)xs)[t] = ((const float4*)(xb + (img + 8 * bi + lrow) * W_))[lcol];
    __syncthreads();
    int rp = t >> 6, j = t & 63;
    float2 top = ((const float2*)(xs + (2 * rp) * W_))[j];
    float2 bot = ((const float2*)(xs + (2 * rp + 1) * W_))[j];
    float p00 = top.x, p01 = top.y, p10 = bot.x, p11 = bot.y;
    float a  = 0.25f * (p00 + p01 + p10 + p11);
    float hb = 0.25f * (p00 - p01 + p10 - p11);
    float vb = 0.25f * (p00 + p01 - p10 - p11);
    float db = 0.25f * (p00 - p01 - p10 + p11);
    int hr = 4 * bi + rp, hc = j;
    int tok = (hr >> 1) * 32 + (hc >> 1);
    float ah = __ldg(&g_alpha[(0 * B_ + b) * TOK_HF + tok]);
    float av = __ldg(&g_alpha[(1 * B_ + b) * TOK_HF + tok]);
    float ad = __ldg(&g_alpha[(2 * B_ + b) * TOK_HF + tok]);
    int tg = (hr >> 2) * 16 + (hc >> 2);
    float gt = __ldg(&g_gate[((size_t)(b * 256 + tg)) * C_ + c]);
    float ae = a * gt, he = hb * ah, ve = vb * av, de = db * ad;
    float2 o0 = make_float2(ae + he + ve + de, ae - he + ve - de);
    float2 o1 = make_float2(ae + he - ve - de, ae - he - ve + de);
    int row0 = 8 * bi + 2 * rp;
    ((float2*)(out + (img + row0) * W_))[j] = o0;
    ((float2*)(out + (img + row0 + 1) * W_))[j] = o1;
}

static constexpr int SMEM_L = (2 * 64 * 68 + 2 * 128 * 68 + 512 + 4) * 4;        // ~104 KB
static constexpr int SMEM_Z = (2 * 64 * 64 + 2 * 256 * 72) * 2 + 512 * 4;        // ~92 KB
static constexpr int SMEM_H2 = (2 * 64 * 72 + 2 * 256 * 72) * 2 + (512 + 4) * 4; // ~92 KB

extern "C" void kernel_launch(void* const* d_in, const int* in_sizes, int n_in,
                              void* d_out, int out_size)
{
    const float* xb      = (const float*)d_in[0];
    const float* xsm     = (const float*)d_in[1];
    const float* hf_w1   = (const float*)d_in[2];
    const float* hf_b1   = (const float*)d_in[3];
    const float* hf_ln_w = (const float*)d_in[4];
    const float* hf_ln_b = (const float*)d_in[5];
    const float* hf_w2   = (const float*)d_in[6];
    const float* hf_b2   = (const float*)d_in[7];
    const float* hf_pr   = (const float*)d_in[8];
    const float* low_w   = (const float*)d_in[9];
    const float* low_b   = (const float*)d_in[10];
    const float* lf_w1   = (const float*)d_in[11];
    const float* lf_b1   = (const float*)d_in[12];
    const float* lf_ln_w = (const float*)d_in[13];
    const float* lf_ln_b = (const float*)d_in[14];
    const float* lf_w2   = (const float*)d_in[15];
    const float* lf_b2   = (const float*)d_in[16];

    void *pz, *pps, *pHh, *pHlf, *pktok, *pgate, *palpha, *pwt, *pwth, *psh, *psl, *pc1, *pbp;
    cudaGetSymbolAddress(&pz, g_z);
    cudaGetSymbolAddress(&pps, g_ps);
    cudaGetSymbolAddress(&pHh, g_Hh);
    cudaGetSymbolAddress(&pHlf, g_Hlf);
    cudaGetSymbolAddress(&pktok, g_ktok);
    cudaGetSymbolAddress(&pgate, g_gate);
    cudaGetSymbolAddress(&palpha, g_alpha);
    cudaGetSymbolAddress(&pwt, g_wt);
    cudaGetSymbolAddress(&pwth, g_wth);
    cudaGetSymbolAddress(&psh, g_stats_hf);
    cudaGetSymbolAddress(&psl, g_stats_lf);
    cudaGetSymbolAddress(&pc1, g_c1);
    cudaGetSymbolAddress(&pbp, g_bp);
    const float* wt = (const float*)pwt;
    const __nv_bfloat16* wth = (const __nv_bfloat16*)pwth;
    float2* sh = (float2*)psh;
    float2* sl = (float2*)psl;
    const float* c1 = (const float*)pc1;
    const float* bp = (const float*)pbp;

    cudaFuncSetAttribute((const void*)gemmz_kernel,
                         cudaFuncAttributeMaxDynamicSharedMemorySize, SMEM_Z);
    cudaFuncSetAttribute((const void*)gemmh2_kernel,
                         cudaFuncAttributeMaxDynamicSharedMemorySize, SMEM_H2);
    cudaFuncSetAttribute((const void*)gemm256_kernel<512, 1, 0, 256, 128, 64, 2>,
                         cudaFuncAttributeMaxDynamicSharedMemorySize, SMEM_L);
    cudaFuncSetAttribute((const void*)gemm256_kernel<256, 2, 1, 512, 128, 64, 4>,
                         cudaFuncAttributeMaxDynamicSharedMemorySize, SMEM_L);
    cudaFuncSetAttribute((const void*)gemm256_kernel<512, 2, 3, 256, 128, 64, 4>,
                         cudaFuncAttributeMaxDynamicSharedMemorySize, SMEM_L);

    // -------- forked-stream schedule (hf chain || lf chain, join at final) --------
    cudaStream_t sH, sL;
    cudaStreamCreateWithFlags(&sH, cudaStreamNonBlocking);
    cudaStreamCreateWithFlags(&sL, cudaStreamNonBlocking);
    cudaEvent_t eStart, eHaar, ePrep, eLf;
    cudaEventCreateWithFlags(&eStart, cudaEventDisableTiming);
    cudaEventCreateWithFlags(&eHaar, cudaEventDisableTiming);
    cudaEventCreateWithFlags(&ePrep, cudaEventDisableTiming);
    cudaEventCreateWithFlags(&eLf, cudaEventDisableTiming);

    // main stream: prep
    transpose5_kernel<<<dim3(16, 16, 5), dim3(32, 8)>>>(hf_w1, hf_w2, low_w, lf_w1, lf_w2,
                                                        hf_ln_w, lf_ln_w);
    cudaEventRecord(eStart, 0);

    // haar on side stream (independent of prep)
    cudaStreamWaitEvent(sH, eStart, 0);
    haar_z_kernel<<<dim3(4, 256, 16), 256, 0, sH>>>(xb);
    cudaEventRecord(eHaar, sH);

    fold_kernel<<<2, 256>>>(hf_w2, hf_ln_b, hf_b2, lf_w2, lf_ln_b, lf_b2);
    cudaEventRecord(ePrep, 0);

    // hf chain on main stream (needs haar + prep)
    cudaStreamWaitEvent(0, eHaar, 0);
    gemmz_kernel<<<dim3(M_HF / 64, 2), 256, SMEM_Z>>>(
        (const __nv_bfloat16*)pz, wth, hf_b1, (__nv_bfloat16*)pHh, sh);
    gemmh2_kernel<<<M_HF / 64, 256, SMEM_H2>>>(
        (const __nv_bfloat16*)pHh, wth + 512 * 256, bp + 0, hf_pr, (float*)palpha, sh, c1 + 0);

    // lf chain on side stream (pool independent; GEMMs need prep)
    cudaStreamWaitEvent(sL, eStart, 0);
    pool_small_kernel<<<dim3(512, 16), 256, 0, sL>>>(xsm);
    cudaStreamWaitEvent(sL, ePrep, 0);
    gemm256_kernel<512, 1, 0, 256, 128, 64, 2><<<dim3(M_LF / 64, 2), 256, SMEM_L, sL>>>(
        (const float*)pps, wt + 2 * 512 * 256, low_b, (float*)pktok, nullptr, nullptr);
    gemm256_kernel<256, 2, 1, 512, 128, 64, 4><<<dim3(M_LF / 64, 4), 256, SMEM_L, sL>>>(
        (const float*)pktok, wt + 3 * 512 * 256, lf_b1, (float*)pHlf, sl, nullptr);
    gemm256_kernel<512, 2, 3, 256, 128, 64, 4><<<dim3(M_LF / 64, 2), 256, SMEM_L, sL>>>(
        (const float*)pHlf, wt + 4 * 512 * 256, bp + 256, (float*)pgate, sl, c1 + 256);
    cudaEventRecord(eLf, sL);

    // join: final needs alpha (main) + gate (sL)
    cudaStreamWaitEvent(0, eLf, 0);
    final_kernel<<<dim3(16, 256, 16), 256>>>(xb, (float*)d_out);

    cudaEventDestroy(eStart);
    cudaEventDestroy(eHaar);
    cudaEventDestroy(ePrep);
    cudaEventDestroy(eLf);
    cudaStreamDestroy(sH);
    cudaStreamDestroy(sL);
}

// round 17
// speedup vs baseline: 1.2256x; 1.0274x over previous
#include <cuda_runtime.h>
#include <cuda_bf16.h>
#include <cstdint>
#include <math.h>

#define DEV_INLINE __device__ __forceinline__

static constexpr int B_ = 16, C_ = 256, H_ = 128, W_ = 128;
static constexpr int CS = 512;
static constexpr int TOK_HF = 1024;
static constexpr int M_HF = 3 * B_ * TOK_HF;     // 49152
static constexpr int M_LF = B_ * 256;            // 4096

// ---------------- scratch ----------------
__device__ __nv_bfloat16 g_z[3ULL * B_ * C_ * TOK_HF];   // [band][b][c][tok] bf16
__device__ float g_ps[(size_t)B_ * CS * 256];            // [b][s][tok]
__device__ __nv_bfloat16 g_Hh[(size_t)M_HF * 512];       // RAW hidden (hf) bf16
__device__ float g_Hlf[(size_t)M_LF * 512];              // RAW hidden (lf) fp32
__device__ float g_ktok[(size_t)M_LF * C_];
__device__ float g_gate[(size_t)M_LF * C_];
__device__ float g_alpha[3 * B_ * TOK_HF];
__device__ float g_wt[5ULL * 512 * 256];                 // transposed weights [n][k] fp32
__device__ __nv_bfloat16 g_wth[2ULL * 512 * 256];        // bf16: [0]=hf_w1t, [1]=hf_w2t'
__device__ float2 g_stats_hf[(size_t)M_HF * 2];
__device__ float2 g_stats_lf[(size_t)M_LF * 4];
__device__ float g_c1[2 * 256];
__device__ float g_bp[2 * 256];

// ---------------- weight transpose (+ LN-weight folding + bf16 copies) ----------------
__global__ void transpose5_kernel(const float* __restrict__ w0, const float* __restrict__ w1,
                                  const float* __restrict__ w2, const float* __restrict__ w3,
                                  const float* __restrict__ w4,
                                  const float* __restrict__ hf_lnw, const float* __restrict__ lf_lnw)
{
    __shared__ float tile[32][33];
    int mi = blockIdx.z;
    const float* in; int R, Cc; const float* lnw = nullptr;
    switch (mi) {
        case 0: in = w0; R = 256; Cc = 512; break;
        case 1: in = w1; R = 512; Cc = 256; lnw = hf_lnw; break;
        case 2: in = w2; R = 512; Cc = 256; break;
        case 3: in = w3; R = 256; Cc = 512; break;
        default: in = w4; R = 512; Cc = 256; lnw = lf_lnw; break;
    }
    float* out = g_wt + (size_t)mi * 512 * 256;
    int bx = blockIdx.x * 32, by = blockIdx.y * 32;
    if (bx >= Cc || by >= R) return;
    int tx = threadIdx.x, ty = threadIdx.y;
#pragma unroll
    for (int j = 0; j < 32; j += 8) {
        int row = by + ty + j;
        float v = in[(size_t)row * Cc + bx + tx];
        if (lnw) v *= __ldg(lnw + row);
        tile[ty + j][tx] = v;
    }
    __syncthreads();
#pragma unroll
    for (int j = 0; j < 32; j += 8) {
        float v = tile[tx][ty + j];
        size_t oidx = (size_t)(bx + ty + j) * R + by + tx;
        out[oidx] = v;
        if (mi == 0) g_wth[oidx] = __float2bfloat16(v);
        if (mi == 1) g_wth[512 * 256 + oidx] = __float2bfloat16(v);
    }
}

__global__ void fold_kernel(const float* __restrict__ w2a, const float* __restrict__ lnba,
                            const float* __restrict__ b2a,
                            const float* __restrict__ w2b, const float* __restrict__ lnbb,
                            const float* __restrict__ b2b)
{
    int mi = blockIdx.x;
    int n = threadIdx.x;
    const float* wt = g_wt + (size_t)(mi ? 4 : 1) * 512 * 256;
    const float* w2 = mi ? w2b : w2a;
    const float* lnb = mi ? lnbb : lnba;
    const float* b2 = mi ? b2b : b2a;
    float s1 = 0.f, s2 = 0.f;
    for (int k = 0; k < 512; k++) {
        s1 += wt[(size_t)n * 512 + k];
        s2 += lnb[k] * w2[(size_t)k * 256 + n];
    }
    g_c1[mi * 256 + n] = s1;
    g_bp[mi * 256 + n] = b2[n] + s2;
}

// ---------------- K1: Haar bands -> abs-pooled z tokens (bf16 out) ----------------
__global__ void haar_z_kernel(const float* __restrict__ xb)
{
    int tid = threadIdx.x;
    int tk = blockIdx.x * 256 + tid;
    int c = blockIdx.y, b = blockIdx.z;
    int ti = tk >> 5, tj = tk & 31;
    const float* base = xb + ((size_t)(b * C_ + c) * H_ + 4 * ti) * W_ + 4 * tj;
    float4 r0 = *(const float4*)(base);
    float4 r1 = *(const float4*)(base + W_);
    float4 r2 = *(const float4*)(base + 2 * W_);
    float4 r3 = *(const float4*)(base + 3 * W_);
    float zh = 0.f, zv = 0.f, zd = 0.f;
#define HBLK(p00, p01, p10, p11) \
    zh += fabsf((p00) - (p01) + (p10) - (p11)); \
    zv += fabsf((p00) + (p01) - (p10) - (p11)); \
    zd += fabsf((p00) - (p01) - (p10) + (p11));
    HBLK(r0.x, r0.y, r1.x, r1.y)
    HBLK(r0.z, r0.w, r1.z, r1.w)
    HBLK(r2.x, r2.y, r3.x, r3.y)
    HBLK(r2.z, r2.w, r3.z, r3.w)
#undef HBLK
    const float s = 0.0625f;
    size_t base_o = ((size_t)(b) * C_ + c) * TOK_HF + tk;
    const size_t BS = (size_t)B_ * C_ * TOK_HF;
    g_z[base_o]          = __float2bfloat16(zh * s);
    g_z[BS + base_o]     = __float2bfloat16(zv * s);
    g_z[2 * BS + base_o] = __float2bfloat16(zd * s);
}

// ---------------- K2: 4x4 mean-pool of x_small ----------------
__global__ void pool_small_kernel(const float* __restrict__ xsm)
{
    int s = blockIdx.x, b = blockIdx.y;
    const float* src = xsm + ((size_t)(b * CS + s)) * 64 * 64;
    int t = threadIdx.x;
    int tj = t & 15, ti = t >> 4;
    float sum = 0.f;
#pragma unroll
    for (int r = 0; r < 4; r++) {
        float4 v = *(const float4*)(src + (4 * ti + r) * 64 + 4 * tj);
        sum += v.x + v.y + v.z + v.w;
    }
    g_ps[((size_t)(b * CS + s)) * 256 + t] = sum * (1.f / 16.f);
}

// ---------------- asm helpers ----------------
DEV_INLINE void mma8(float* c, const unsigned* a, const unsigned* b) {
    asm volatile("mma.sync.aligned.m16n8k8.row.col.f32.tf32.tf32.f32 "
                 "{%0,%1,%2,%3}, {%4,%5,%6,%7}, {%8,%9}, {%0,%1,%2,%3};"
                 : "+f"(c[0]), "+f"(c[1]), "+f"(c[2]), "+f"(c[3])
                 : "r"(a[0]), "r"(a[1]), "r"(a[2]), "r"(a[3]),
                   "r"(b[0]), "r"(b[1]));
}
DEV_INLINE void mma16(float* c, const unsigned* a, const unsigned* b) {
    asm volatile("mma.sync.aligned.m16n8k16.row.col.f32.bf16.bf16.f32 "
                 "{%0,%1,%2,%3}, {%4,%5,%6,%7}, {%8,%9}, {%0,%1,%2,%3};"
                 : "+f"(c[0]), "+f"(c[1]), "+f"(c[2]), "+f"(c[3])
                 : "r"(a[0]), "r"(a[1]), "r"(a[2]), "r"(a[3]),
                   "r"(b[0]), "r"(b[1]));
}
DEV_INLINE void ldsm4(unsigned& r0, unsigned& r1, unsigned& r2, unsigned& r3, uint32_t addr) {
    asm volatile("ldmatrix.sync.aligned.m8n8.x4.shared.b16 {%0,%1,%2,%3}, [%4];"
                 : "=r"(r0), "=r"(r1), "=r"(r2), "=r"(r3) : "r"(addr));
}
DEV_INLINE void ldsm4t(unsigned& r0, unsigned& r1, unsigned& r2, unsigned& r3, uint32_t addr) {
    asm volatile("ldmatrix.sync.aligned.m8n8.x4.trans.shared.b16 {%0,%1,%2,%3}, [%4];"
                 : "=r"(r0), "=r"(r1), "=r"(r2), "=r"(r3) : "r"(addr));
}
DEV_INLINE void cp16(uint32_t s, const void* g) {
    asm volatile("cp.async.cg.shared.global [%0], [%1], 16;" :: "r"(s), "l"(g));
}
DEV_INLINE void cp_commit() { asm volatile("cp.async.commit_group;"); }
template<int NN> DEV_INLINE void cp_wait() { asm volatile("cp.async.wait_group %0;" :: "n"(NN)); }

// ---------------- tf32 64xNN-tile GEMM, generic NN/KC (lf chain) ----------------
template<int K, int AMODE, int EPI, int OSTRIDE, int NN, int KC, int NST>
__global__ void __launch_bounds__(256, 2)
gemm256_kernel(const float* __restrict__ A, const float* __restrict__ Bt,
               const float* __restrict__ bias, float* __restrict__ out,
               float2* __restrict__ stats, const float* __restrict__ c1)
{
    constexpr int SW = KC + 4, SWB = SW * 4, NIT = K / KC;
    constexpr int MT = 2, NT = NN / 32;
    constexpr int CPR = KC / 4;

    extern __shared__ __align__(16) float dsm[];
    float* As = dsm;
    float* Bs = As + 2 * 64 * SW;
    float* sred = Bs + 2 * NN * SW;
    float* ssred = sred + 256;

    int tid = threadIdx.x;
    int lane = tid & 31, warp = tid >> 5;
    int wn = warp & 3, wm = warp >> 2;
    int gid = lane >> 2, q4 = lane & 3;
    int m0 = blockIdx.x * 64;
    int n0 = blockIdx.y * NN;

    const float* Ab; int astride = 0;
    if (AMODE == 1) { Ab = A + (size_t)(m0 >> 8) * (CS * 256) + (m0 & 255); astride = 256; }
    else { Ab = A + (size_t)m0 * K; }
    const float* BtB = Bt + (size_t)n0 * K;

    uint32_t smem_a = (uint32_t)__cvta_generic_to_shared(As);
    uint32_t smem_b = (uint32_t)__cvta_generic_to_shared(Bs);

    int la_m = tid & 63, la_kg = tid >> 6;
    float areg[CPR];
    auto load_A = [&](int k0) {
        if (AMODE == 1) {
#pragma unroll
            for (int i = 0; i < CPR; i++)
                areg[i] = __ldg(Ab + (size_t)(k0 + la_kg * CPR + i) * astride + la_m);
        }
    };
    auto sts_A = [&](int st) {
        if (AMODE == 1) {
            float* p = As + st * 64 * SW + la_m * SW + la_kg * CPR;
#pragma unroll
            for (int i = 0; i < CPR; i += 4)
                *(float4*)(p + i) = make_float4(areg[i], areg[i + 1], areg[i + 2], areg[i + 3]);
        }
    };
    auto cp_stage = [&](int st, int k0) {
        if (AMODE == 2) {
#pragma unroll
            for (int j = 0; j < 64 * CPR / 256; j++) {
                int idx = tid + j * 256;
                int m = idx / CPR, kq = idx % CPR;
                cp16(smem_a + (uint32_t)((st * 64 + m) * SW + kq * 4) * 4,
                     Ab + (size_t)m * K + k0 + kq * 4);
            }
        }
#pragma unroll
        for (int j = 0; j < NN * CPR / 256; j++) {
            int idx = tid + j * 256;
            int n = idx / CPR, kc = idx % CPR;
            cp16(smem_b + (uint32_t)((st * NN + n) * SW + kc * 4) * 4,
                 BtB + (size_t)n * K + k0 + kc * 4);
        }
        cp_commit();
    };

    int ra = lane & 15;
    int ca = (lane & 16) ? 16 : 0;
    int rb = (lane & 7) + ((lane >> 4) << 3);
    int cb = (lane & 8) ? 16 : 0;

    float acc[MT][NT][4];
#pragma unroll
    for (int mi = 0; mi < MT; mi++)
#pragma unroll
        for (int ni = 0; ni < NT; ni++)
#pragma unroll
            for (int e = 0; e < 4; e++) acc[mi][ni][e] = 0.f;

    load_A(0);
    cp_stage(0, 0);
    sts_A(0);
    if (NIT > 1) load_A(KC);

    for (int it = 0; it < NIT; it++) {
        int cur = it & 1;
        bool more = (it + 1 < NIT);
        cp_wait<0>();
        __syncthreads();
        if (more) {
            cp_stage(cur ^ 1, (it + 1) * KC);
            sts_A(cur ^ 1);
        }
        if (it + 2 < NIT) load_A((it + 2) * KC);

        uint32_t abase = smem_a + (uint32_t)(cur * 64 * SW) * 4;
        uint32_t bbase = smem_b + (uint32_t)(cur * NN * SW) * 4;
#pragma unroll
        for (int kk = 0; kk < KC; kk += 8) {
            unsigned afr[MT][4];
#pragma unroll
            for (int mi = 0; mi < MT; mi++)
                ldsm4(afr[mi][0], afr[mi][1], afr[mi][2], afr[mi][3],
                      abase + (uint32_t)((wm * 32 + mi * 16 + ra) * SWB + kk * 4 + ca));
            unsigned bfr[NT][2];
#pragma unroll
            for (int nis = 0; nis < NT; nis += 2)
                ldsm4(bfr[nis][0], bfr[nis][1], bfr[nis + 1][0], bfr[nis + 1][1],
                      bbase + (uint32_t)((wn * (NN / 4) + nis * 8 + rb) * SWB + kk * 4 + cb));
#pragma unroll
            for (int mi = 0; mi < MT; mi++)
#pragma unroll
                for (int ni = 0; ni < NT; ni++)
                    mma8(acc[mi][ni], afr[mi], bfr[ni]);
        }
    }

    float mu_rs[MT][2], rstd_v[MT][2];
    if (EPI == 3) {
#pragma unroll
        for (int mi = 0; mi < MT; mi++)
#pragma unroll
            for (int h = 0; h < 2; h++) {
                int lr = wm * 32 + mi * 16 + gid + h * 8;
                float sum = 0.f, ss = 0.f;
#pragma unroll
                for (int j = 0; j < NST; j++) {
                    float2 s = stats[(size_t)(m0 + lr) * NST + j];
                    sum += s.x; ss += s.y;
                }
                float mu = sum * (1.f / 512.f);
                float var = ss * (1.f / 512.f) - mu * mu;
                float rstd = rsqrtf(var + 1e-5f);
                rstd_v[mi][h] = rstd;
                mu_rs[mi][h] = mu * rstd;
            }
    }

    float rs[MT][2], rss[MT][2];
#pragma unroll
    for (int mi = 0; mi < MT; mi++) { rs[mi][0] = rs[mi][1] = 0.f; rss[mi][0] = rss[mi][1] = 0.f; }

#pragma unroll
    for (int mi = 0; mi < MT; mi++)
#pragma unroll
        for (int ni = 0; ni < NT; ni++)
#pragma unroll
            for (int e4 = 0; e4 < 4; e4++) {
                int h = e4 >> 1, e = e4 & 1;
                int col = wn * (NN / 4) + ni * 8 + q4 * 2 + e;
                float v;
                if (EPI <= 1) {
                    v = acc[mi][ni][e4] + __ldg(bias + n0 + col);
                    if (EPI == 1) { rs[mi][h] += v; rss[mi][h] += v * v; }
                } else {
                    v = rstd_v[mi][h] * acc[mi][ni][e4] - mu_rs[mi][h] * __ldg(c1 + n0 + col)
                        + __ldg(bias + n0 + col);
                }
                acc[mi][ni][e4] = v;
            }

    if (EPI == 1) {
#pragma unroll
        for (int mi = 0; mi < MT; mi++)
#pragma unroll
            for (int h = 0; h < 2; h++) {
                float s = rs[mi][h], ss = rss[mi][h];
                s  += __shfl_xor_sync(0xffffffffu, s, 1);
                s  += __shfl_xor_sync(0xffffffffu, s, 2);
                ss += __shfl_xor_sync(0xffffffffu, ss, 1);
                ss += __shfl_xor_sync(0xffffffffu, ss, 2);
                if (q4 == 0) {
                    int lr = wm * 32 + mi * 16 + gid + h * 8;
                    sred[lr * 4 + wn] = s; ssred[lr * 4 + wn] = ss;
                }
            }
        __syncthreads();
    }

#pragma unroll
    for (int mi = 0; mi < MT; mi++)
#pragma unroll
        for (int ni = 0; ni < NT; ni++) {
            int col = wn * (NN / 4) + ni * 8 + q4 * 2;
#pragma unroll
            for (int h = 0; h < 2; h++) {
                int lr = wm * 32 + mi * 16 + gid + h * 8;
                float vx = acc[mi][ni][h * 2 + 0], vy = acc[mi][ni][h * 2 + 1];
                if (EPI == 3) { vx = 1.f / (1.f + expf(-vx)); vy = 1.f / (1.f + expf(-vy)); }
                *(float2*)(out + (size_t)(m0 + lr) * OSTRIDE + n0 + col) = make_float2(vx, vy);
            }
        }
    if (EPI == 1) {
        if (tid < 64) {
            float s = 0.f, ss = 0.f;
#pragma unroll
            for (int j = 0; j < 4; j++) { s += sred[tid * 4 + j]; ss += ssred[tid * 4 + j]; }
            stats[(size_t)(m0 + tid) * NST + blockIdx.y] = make_float2(s, ss);
        }
    }
}

// ---------------- bf16 GEMM1-hf with cp.async A + ldmatrix.trans (R14-proven) ----------------
// moff0: M-row offset (split-M pipelining). Grid x covers a half.
__global__ void __launch_bounds__(256, 2)
gemmz_kernel(const __nv_bfloat16* __restrict__ Z, const __nv_bfloat16* __restrict__ Bt,
             const float* __restrict__ bias, __nv_bfloat16* __restrict__ outH,
             float2* __restrict__ stats, int moff0)
{
    constexpr int KC = 64, NIT = 256 / KC;
    constexpr int SWBH = 72;
    constexpr int MT = 2;

    extern __shared__ __align__(16) char dsmz[];
    __nv_bfloat16* As = (__nv_bfloat16*)dsmz;
    __nv_bfloat16* Bs = As + 2 * 64 * 64;
    float* sred = (float*)(Bs + 2 * 256 * SWBH);
    float* ssred = sred + 256;

    int tid = threadIdx.x;
    int lane = tid & 31, warp = tid >> 5;
    int wn = warp & 3, wm = warp >> 2;
    int gid = lane >> 2, q4 = lane & 3;
    int m0 = moff0 + blockIdx.x * 64;
    int n0 = blockIdx.y * 256;

    const __nv_bfloat16* Ab = Z + (size_t)(m0 >> 10) * (C_ * TOK_HF) + (m0 & 1023);
    const __nv_bfloat16* BtB = Bt + (size_t)n0 * 256;

    uint32_t smem_a = (uint32_t)__cvta_generic_to_shared(As);
    uint32_t smem_b = (uint32_t)__cvta_generic_to_shared(Bs);

    auto cp_stage = [&](int st, int k0) {
#pragma unroll
        for (int j = 0; j < 2; j++) {
            int idx = tid + j * 256;
            int k = idx >> 3, mc = idx & 7;
            cp16(smem_a + (uint32_t)((st * 64 + k) * 128 + ((mc * 16) ^ ((k & 7) << 4))),
                 Ab + (size_t)(k0 + k) * TOK_HF + mc * 8);
        }
#pragma unroll
        for (int j = 0; j < 8; j++) {
            int idx = tid + j * 256;
            int n = idx >> 3, kc = idx & 7;
            cp16(smem_b + (uint32_t)((st * 256 + n) * SWBH + kc * 8) * 2,
                 BtB + (size_t)n * 256 + k0 + kc * 8);
        }
        cp_commit();
    };

    int ksrc = (lane & 7) + ((lane >> 4) << 3);
    int moff = ((lane >> 3) & 1) << 3;
    int rb = (lane & 7) + ((lane >> 4) << 3);
    int cb = (lane & 8) ? 16 : 0;

    float acc[MT][8][4];
#pragma unroll
    for (int mi = 0; mi < MT; mi++)
#pragma unroll
        for (int ni = 0; ni < 8; ni++)
#pragma unroll
            for (int e = 0; e < 4; e++) acc[mi][ni][e] = 0.f;

    cp_stage(0, 0);

    for (int it = 0; it < NIT; it++) {
        int cur = it & 1;
        bool more = (it + 1 < NIT);
        cp_wait<0>();
        __syncthreads();
        if (more) cp_stage(cur ^ 1, (it + 1) * KC);

        uint32_t abase = smem_a + (uint32_t)(cur * 64 * 128);
        uint32_t bbase = smem_b + (uint32_t)(cur * 256 * SWBH) * 2;
#pragma unroll
        for (int kk = 0; kk < 4; kk++) {
            int krow = kk * 16 + ksrc;
            unsigned afr[MT][4];
#pragma unroll
            for (int mi = 0; mi < MT; mi++) {
                int mb = (wm * 32 + mi * 16 + moff) * 2;
                ldsm4t(afr[mi][0], afr[mi][1], afr[mi][2], afr[mi][3],
                       abase + (uint32_t)(krow * 128 + (mb ^ ((ksrc & 7) << 4))));
            }
            unsigned bfr[8][2];
#pragma unroll
            for (int nis = 0; nis < 8; nis += 2)
                ldsm4(bfr[nis][0], bfr[nis][1], bfr[nis + 1][0], bfr[nis + 1][1],
                      bbase + (uint32_t)((wn * 64 + nis * 8 + rb) * (SWBH * 2) + cb + kk * 32));
#pragma unroll
            for (int mi = 0; mi < MT; mi++)
#pragma unroll
                for (int ni = 0; ni < 8; ni++)
                    mma16(acc[mi][ni], afr[mi], bfr[ni]);
        }
    }

    float rs[MT][2], rss[MT][2];
#pragma unroll
    for (int mi = 0; mi < MT; mi++) { rs[mi][0] = rs[mi][1] = 0.f; rss[mi][0] = rss[mi][1] = 0.f; }
#pragma unroll
    for (int mi = 0; mi < MT; mi++)
#pragma unroll
        for (int ni = 0; ni < 8; ni++)
#pragma unroll
            for (int e4 = 0; e4 < 4; e4++) {
                int h = e4 >> 1, e = e4 & 1;
                int col = wn * 64 + ni * 8 + q4 * 2 + e;
                float v = acc[mi][ni][e4] + __ldg(bias + n0 + col);
                rs[mi][h] += v; rss[mi][h] += v * v;
                acc[mi][ni][e4] = v;
            }
#pragma unroll
    for (int mi = 0; mi < MT; mi++)
#pragma unroll
        for (int h = 0; h < 2; h++) {
            float s = rs[mi][h], ss = rss[mi][h];
            s  += __shfl_xor_sync(0xffffffffu, s, 1);
            s  += __shfl_xor_sync(0xffffffffu, s, 2);
            ss += __shfl_xor_sync(0xffffffffu, ss, 1);
            ss += __shfl_xor_sync(0xffffffffu, ss, 2);
            if (q4 == 0) {
                int lr = wm * 32 + mi * 16 + gid + h * 8;
                sred[lr * 4 + wn] = s; ssred[lr * 4 + wn] = ss;
            }
        }
    __syncthreads();
#pragma unroll
    for (int mi = 0; mi < MT; mi++)
#pragma unroll
        for (int ni = 0; ni < 8; ni++) {
            int col = wn * 64 + ni * 8 + q4 * 2;
#pragma unroll
            for (int h = 0; h < 2; h++) {
                int lr = wm * 32 + mi * 16 + gid + h * 8;
                *(__nv_bfloat162*)(outH + (size_t)(m0 + lr) * 512 + n0 + col) =
                    __floats2bfloat162_rn(acc[mi][ni][h * 2 + 0], acc[mi][ni][h * 2 + 1]);
            }
        }
    if (tid < 64) {
        float s = 0.f, ss = 0.f;
#pragma unroll
        for (int j = 0; j < 4; j++) { s += sred[tid * 4 + j]; ss += ssred[tid * 4 + j]; }
        stats[(size_t)(m0 + tid) * 2 + blockIdx.y] = make_float2(s, ss);
    }
}

// ---------------- bf16 hf GEMM2 (R14-proven; moff0 for split-M) ----------------
__global__ void __launch_bounds__(256, 2)
gemmh2_kernel(const __nv_bfloat16* __restrict__ A, const __nv_bfloat16* __restrict__ Bt,
              const float* __restrict__ bias, const float* __restrict__ p0,
              float* __restrict__ outv, float2* __restrict__ stats,
              const float* __restrict__ c1, int moff0)
{
    constexpr int K = 512, KC = 64, SW = 72, SWB = SW * 2, NIT = K / KC, NN = 256;
    constexpr int MT = 2;

    extern __shared__ __align__(16) char dsmh[];
    __nv_bfloat16* As = (__nv_bfloat16*)dsmh;
    __nv_bfloat16* Bs = As + 2 * 64 * SW;
    float* sred = (float*)(Bs + 2 * NN * SW);
    float* ssred = sred + 256;
    float* spn = ssred + 256;

    int tid = threadIdx.x;
    int lane = tid & 31, warp = tid >> 5;
    int wn = warp & 3, wm = warp >> 2;
    int gid = lane >> 2, q4 = lane & 3;
    int m0 = moff0 + blockIdx.x * 64;

    const __nv_bfloat16* Ab = A + (size_t)m0 * K;
    const __nv_bfloat16* BtB = Bt;

    if (warp == 0) {
        float s = 0.f;
        for (int i = lane; i < 256; i += 32) { float v = __ldg(p0 + i); s += v * v; }
#pragma unroll
        for (int o = 16; o; o >>= 1) s += __shfl_xor_sync(0xffffffffu, s, o);
        if (lane == 0) *spn = sqrtf(s);
    }

    uint32_t smem_a = (uint32_t)__cvta_generic_to_shared(As);
    uint32_t smem_b = (uint32_t)__cvta_generic_to_shared(Bs);

    auto cp_stage = [&](int st, int k0) {
#pragma unroll
        for (int j = 0; j < 2; j++) {
            int idx = tid + j * 256;
            int m = idx >> 3, kq = idx & 7;
            cp16(smem_a + (uint32_t)((st * 64 + m) * SW + kq * 8) * 2,
                 Ab + (size_t)m * K + k0 + kq * 8);
        }
#pragma unroll
        for (int j = 0; j < 8; j++) {
            int idx = tid + j * 256;
            int n = idx >> 3, kc = idx & 7;
            cp16(smem_b + (uint32_t)((st * NN + n) * SW + kc * 8) * 2,
                 BtB + (size_t)n * K + k0 + kc * 8);
        }
        cp_commit();
    };

    int ra = lane & 15;
    int ca = (lane >> 4) * 16;
    int rb = (lane & 7) + ((lane >> 4) << 3);
    int cb = (lane & 8) ? 16 : 0;

    float acc[MT][8][4];
#pragma unroll
    for (int mi = 0; mi < MT; mi++)
#pragma unroll
        for (int ni = 0; ni < 8; ni++)
#pragma unroll
            for (int e = 0; e < 4; e++) acc[mi][ni][e] = 0.f;

    cp_stage(0, 0);

    for (int it = 0; it < NIT; it++) {
        int cur = it & 1;
        bool more = (it + 1 < NIT);
        cp_wait<0>();
        __syncthreads();
        if (more) cp_stage(cur ^ 1, (it + 1) * KC);

        uint32_t abase = smem_a + (uint32_t)(cur * 64 * SW) * 2;
        uint32_t bbase = smem_b + (uint32_t)(cur * NN * SW) * 2;
#pragma unroll
        for (int kk = 0; kk < 4; kk++) {
            unsigned afr[MT][4];
#pragma unroll
            for (int mi = 0; mi < MT; mi++)
                ldsm4(afr[mi][0], afr[mi][1], afr[mi][2], afr[mi][3],
                      abase + (uint32_t)((wm * 32 + mi * 16 + ra) * SWB + ca + kk * 32));
            unsigned bfr[8][2];
#pragma unroll
            for (int nis = 0; nis < 8; nis += 2)
                ldsm4(bfr[nis][0], bfr[nis][1], bfr[nis + 1][0], bfr[nis + 1][1],
                      bbase + (uint32_t)((wn * 64 + nis * 8 + rb) * SWB + cb + kk * 32));
#pragma unroll
            for (int mi = 0; mi < MT; mi++)
#pragma unroll
                for (int ni = 0; ni < 8; ni++)
                    mma16(acc[mi][ni], afr[mi], bfr[ni]);
        }
    }

    float mu_rs[MT][2], rstd_v[MT][2];
#pragma unroll
    for (int mi = 0; mi < MT; mi++)
#pragma unroll
        for (int h = 0; h < 2; h++) {
            int lr = wm * 32 + mi * 16 + gid + h * 8;
            float2 s0 = stats[(size_t)(m0 + lr) * 2 + 0];
            float2 s1 = stats[(size_t)(m0 + lr) * 2 + 1];
            float sum = s0.x + s1.x, ss = s0.y + s1.y;
            float mu = sum * (1.f / 512.f);
            float var = ss * (1.f / 512.f) - mu * mu;
            float rstd = rsqrtf(var + 1e-5f);
            rstd_v[mi][h] = rstd;
            mu_rs[mi][h] = mu * rstd;
        }

    float rs[MT][2], rss[MT][2];
#pragma unroll
    for (int mi = 0; mi < MT; mi++) { rs[mi][0] = rs[mi][1] = 0.f; rss[mi][0] = rss[mi][1] = 0.f; }
#pragma unroll
    for (int mi = 0; mi < MT; mi++)
#pragma unroll
        for (int ni = 0; ni < 8; ni++)
#pragma unroll
            for (int e4 = 0; e4 < 4; e4++) {
                int h = e4 >> 1, e = e4 & 1;
                int col = wn * 64 + ni * 8 + q4 * 2 + e;
                float v = rstd_v[mi][h] * acc[mi][ni][e4] - mu_rs[mi][h] * __ldg(c1 + col)
                          + __ldg(bias + col);
                rs[mi][h] += v * __ldg(p0 + col);
                rss[mi][h] += v * v;
            }
#pragma unroll
    for (int mi = 0; mi < MT; mi++)
#pragma unroll
        for (int h = 0; h < 2; h++) {
            float s = rs[mi][h], ss = rss[mi][h];
            s  += __shfl_xor_sync(0xffffffffu, s, 1);
            s  += __shfl_xor_sync(0xffffffffu, s, 2);
            ss += __shfl_xor_sync(0xffffffffu, ss, 1);
            ss += __shfl_xor_sync(0xffffffffu, ss, 2);
            if (q4 == 0) {
                int lr = wm * 32 + mi * 16 + gid + h * 8;
                sred[lr * 4 + wn] = s; ssred[lr * 4 + wn] = ss;
            }
        }
    __syncthreads();
    if (tid < 64) {
        float dot = 0.f, nsq = 0.f;
#pragma unroll
        for (int j = 0; j < 4; j++) { dot += sred[tid * 4 + j]; nsq += ssred[tid * 4 + j]; }
        float nq = sqrtf(nsq);
        float sim = dot / (fmaxf(nq, 1e-8f) * fmaxf(*spn, 1e-8f));
        outv[m0 + tid] = fmaxf(sim, 0.f);
    }
}

// ---------------- K5: apply alpha/gate, inverse Haar, write output ----------------
__global__ void final_kernel(const float* __restrict__ xb, float* __restrict__ out)
{
    __shared__ __align__(16) float xs[8 * 128];
    int bi = blockIdx.x, c = blockIdx.y, b = blockIdx.z;
    size_t img = ((size_t)(b * C_ + c)) * H_;
    int t = threadIdx.x;
    int lrow = t >> 5, lcol = t & 31;
    ((float4*)xs)[t] = ((const float4*)(xb + (img + 8 * bi + lrow) * W_))[lcol];
    __syncthreads();
    int rp = t >> 6, j = t & 63;
    float2 top = ((const float2*)(xs + (2 * rp) * W_))[j];
    float2 bot = ((const float2*)(xs + (2 * rp + 1) * W_))[j];
    float p00 = top.x, p01 = top.y, p10 = bot.x, p11 = bot.y;
    float a  = 0.25f * (p00 + p01 + p10 + p11);
    float hb = 0.25f * (p00 - p01 + p10 - p11);
    float vb = 0.25f * (p00 + p01 - p10 - p11);
    float db = 0.25f * (p00 - p01 - p10 + p11);
    int hr = 4 * bi + rp, hc = j;
    int tok = (hr >> 1) * 32 + (hc >> 1);
    float ah = __ldg(&g_alpha[(0 * B_ + b) * TOK_HF + tok]);
    float av = __ldg(&g_alpha[(1 * B_ + b) * TOK_HF + tok]);
    float ad = __ldg(&g_alpha[(2 * B_ + b) * TOK_HF + tok]);
    int tg = (hr >> 2) * 16 + (hc >> 2);
    float gt = __ldg(&g_gate[((size_t)(b * 256 + tg)) * C_ + c]);
    float ae = a * gt, he = hb * ah, ve = vb * av, de = db * ad;
    float2 o0 = make_float2(ae + he + ve + de, ae - he + ve - de);
    float2 o1 = make_float2(ae + he - ve - de, ae - he - ve + de);
    int row0 = 8 * bi + 2 * rp;
    ((float2*)(out + (img + row0) * W_))[j] = o0;
    ((float2*)(out + (img + row0 + 1) * W_))[j] = o1;
}

static constexpr int SMEM_L = (2 * 64 * 68 + 2 * 128 * 68 + 512 + 4) * 4;
static constexpr int SMEM_Z = (2 * 64 * 64 + 2 * 256 * 72) * 2 + 512 * 4;
static constexpr int SMEM_H2 = (2 * 64 * 72 + 2 * 256 * 72) * 2 + (512 + 4) * 4;
static constexpr int MHALF = M_HF / 2;   // 24576

extern "C" void kernel_launch(void* const* d_in, const int* in_sizes, int n_in,
                              void* d_out, int out_size)
{
    const float* xb      = (const float*)d_in[0];
    const float* xsm     = (const float*)d_in[1];
    const float* hf_w1   = (const float*)d_in[2];
    const float* hf_b1   = (const float*)d_in[3];
    const float* hf_ln_w = (const float*)d_in[4];
    const float* hf_ln_b = (const float*)d_in[5];
    const float* hf_w2   = (const float*)d_in[6];
    const float* hf_b2   = (const float*)d_in[7];
    const float* hf_pr   = (const float*)d_in[8];
    const float* low_w   = (const float*)d_in[9];
    const float* low_b   = (const float*)d_in[10];
    const float* lf_w1   = (const float*)d_in[11];
    const float* lf_b1   = (const float*)d_in[12];
    const float* lf_ln_w = (const float*)d_in[13];
    const float* lf_ln_b = (const float*)d_in[14];
    const float* lf_w2   = (const float*)d_in[15];
    const float* lf_b2   = (const float*)d_in[16];

    void *pz, *pps, *pHh, *pHlf, *pktok, *pgate, *palpha, *pwt, *pwth, *psh, *psl, *pc1, *pbp;
    cudaGetSymbolAddress(&pz, g_z);
    cudaGetSymbolAddress(&pps, g_ps);
    cudaGetSymbolAddress(&pHh, g_Hh);
    cudaGetSymbolAddress(&pHlf, g_Hlf);
    cudaGetSymbolAddress(&pktok, g_ktok);
    cudaGetSymbolAddress(&pgate, g_gate);
    cudaGetSymbolAddress(&palpha, g_alpha);
    cudaGetSymbolAddress(&pwt, g_wt);
    cudaGetSymbolAddress(&pwth, g_wth);
    cudaGetSymbolAddress(&psh, g_stats_hf);
    cudaGetSymbolAddress(&psl, g_stats_lf);
    cudaGetSymbolAddress(&pc1, g_c1);
    cudaGetSymbolAddress(&pbp, g_bp);
    const float* wt = (const float*)pwt;
    const __nv_bfloat16* wth = (const __nv_bfloat16*)pwth;
    float2* sh = (float2*)psh;
    float2* sl = (float2*)psl;
    const float* c1 = (const float*)pc1;
    const float* bp = (const float*)pbp;

    cudaFuncSetAttribute((const void*)gemmz_kernel,
                         cudaFuncAttributeMaxDynamicSharedMemorySize, SMEM_Z);
    cudaFuncSetAttribute((const void*)gemmh2_kernel,
                         cudaFuncAttributeMaxDynamicSharedMemorySize, SMEM_H2);
    cudaFuncSetAttribute((const void*)gemm256_kernel<512, 1, 0, 256, 128, 64, 2>,
                         cudaFuncAttributeMaxDynamicSharedMemorySize, SMEM_L);
    cudaFuncSetAttribute((const void*)gemm256_kernel<256, 2, 1, 512, 128, 64, 4>,
                         cudaFuncAttributeMaxDynamicSharedMemorySize, SMEM_L);
    cudaFuncSetAttribute((const void*)gemm256_kernel<512, 2, 3, 256, 128, 64, 4>,
                         cudaFuncAttributeMaxDynamicSharedMemorySize, SMEM_L);

    // -------- forked-stream schedule: haar || prep; lf chain || hf chain;
    //          split-M pipelined gemmz/gemmh2; join at final --------
    cudaStream_t sH, sL, sP;
    cudaStreamCreateWithFlags(&sH, cudaStreamNonBlocking);
    cudaStreamCreateWithFlags(&sL, cudaStreamNonBlocking);
    cudaStreamCreateWithFlags(&sP, cudaStreamNonBlocking);
    cudaEvent_t eStart, eHaar, ePrep, eLf, eZA, eZB, eH2;
    cudaEventCreateWithFlags(&eStart, cudaEventDisableTiming);
    cudaEventCreateWithFlags(&eHaar, cudaEventDisableTiming);
    cudaEventCreateWithFlags(&ePrep, cudaEventDisableTiming);
    cudaEventCreateWithFlags(&eLf, cudaEventDisableTiming);
    cudaEventCreateWithFlags(&eZA, cudaEventDisableTiming);
    cudaEventCreateWithFlags(&eZB, cudaEventDisableTiming);
    cudaEventCreateWithFlags(&eH2, cudaEventDisableTiming);

    // fork immediately: haar runs concurrently with weight prep
    cudaEventRecord(eStart, 0);
    cudaStreamWaitEvent(sH, eStart, 0);
    haar_z_kernel<<<dim3(4, 256, 16), 256, 0, sH>>>(xb);
    cudaEventRecord(eHaar, sH);

    cudaStreamWaitEvent(sL, eStart, 0);
    pool_small_kernel<<<dim3(512, 16), 256, 0, sL>>>(xsm);

    transpose5_kernel<<<dim3(16, 16, 5), dim3(32, 8)>>>(hf_w1, hf_w2, low_w, lf_w1, lf_w2,
                                                        hf_ln_w, lf_ln_w);
    fold_kernel<<<2, 256>>>(hf_w2, hf_ln_b, hf_b2, lf_w2, lf_ln_b, lf_b2);
    cudaEventRecord(ePrep, 0);

    // hf chain, split-M pipelined: gemmzA -> gemmzB (main), gemmh2A overlaps gemmzB (sP)
    cudaStreamWaitEvent(0, eHaar, 0);
    gemmz_kernel<<<dim3(MHALF / 64, 2), 256, SMEM_Z>>>(
        (const __nv_bfloat16*)pz, wth, hf_b1, (__nv_bfloat16*)pHh, sh, 0);
    cudaEventRecord(eZA, 0);
    gemmz_kernel<<<dim3(MHALF / 64, 2), 256, SMEM_Z>>>(
        (const __nv_bfloat16*)pz, wth, hf_b1, (__nv_bfloat16*)pHh, sh, MHALF);
    cudaEventRecord(eZB, 0);

    cudaStreamWaitEvent(sP, eZA, 0);
    gemmh2_kernel<<<MHALF / 64, 256, SMEM_H2, sP>>>(
        (const __nv_bfloat16*)pHh, wth + 512 * 256, bp + 0, hf_pr, (float*)palpha, sh, c1 + 0, 0);
    cudaStreamWaitEvent(sP, eZB, 0);
    gemmh2_kernel<<<MHALF / 64, 256, SMEM_H2, sP>>>(
        (const __nv_bfloat16*)pHh, wth + 512 * 256, bp + 0, hf_pr, (float*)palpha, sh, c1 + 0,
        MHALF);
    cudaEventRecord(eH2, sP);

    // lf chain on sL (GEMMs need prep)
    cudaStreamWaitEvent(sL, ePrep, 0);
    gemm256_kernel<512, 1, 0, 256, 128, 64, 2><<<dim3(M_LF / 64, 2), 256, SMEM_L, sL>>>(
        (const float*)pps, wt + 2 * 512 * 256, low_b, (float*)pktok, nullptr, nullptr);
    gemm256_kernel<256, 2, 1, 512, 128, 64, 4><<<dim3(M_LF / 64, 4), 256, SMEM_L, sL>>>(
        (const float*)pktok, wt + 3 * 512 * 256, lf_b1, (float*)pHlf, sl, nullptr);
    gemm256_kernel<512, 2, 3, 256, 128, 64, 4><<<dim3(M_LF / 64, 2), 256, SMEM_L, sL>>>(
        (const float*)pHlf, wt + 4 * 512 * 256, bp + 256, (float*)pgate, sl, c1 + 256);
    cudaEventRecord(eLf, sL);

    // join: final needs alpha (sP) + gate (sL)
    cudaStreamWaitEvent(0, eH2, 0);
    cudaStreamWaitEvent(0, eLf, 0);
    final_kernel<<<dim3(16, 256, 16), 256>>>(xb, (float*)d_out);

    cudaEventDestroy(eStart);
    cudaEventDestroy(eHaar);
    cudaEventDestroy(ePrep);
    cudaEventDestroy(eLf);
    cudaEventDestroy(eZA);
    cudaEventDestroy(eZB);
    cudaEventDestroy(eH2);
    cudaStreamDestroy(sH);
    cudaStreamDestroy(sL);
    cudaStreamDestroy(sP);
}